// round 8
// baseline (speedup 1.0000x reference)
#include <cuda_runtime.h>
#include <math.h>
#include <stdint.h>

#define NB 512
#define NH 1024
#define NS 64
#define NM 10
#define CAT_LD 1056
#define NBNH (NB * NH)
#define G3 (3 * NH)

// ---------------- scratch (device globals) ----------------------------------
__device__ __align__(1024) float g_Wt[NH * NH];
__device__ __align__(1024) float g_preW[NH * CAT_LD];
__device__ __align__(1024) float g_upart[4 * NBNH];
__device__ __align__(1024) float g_cat[NB * CAT_LD];
__device__ __align__(1024) float g_xpart[6 * NBNH];
__device__ __align__(1024) float g_x0[NBNH];
__device__ __align__(1024) float g_giA[NB * G3];
__device__ __align__(1024) float g_giB[NB * G3];
__device__ __align__(1024) float g_ghA[NB * G3];
__device__ __align__(1024) float g_ghB[NB * G3];

__device__ unsigned g_barr[8];
__device__ unsigned g_sense[8];

// ---------------- global barrier (all CTAs co-resident by construction) -----
__device__ __forceinline__ void gbar(int id, unsigned total) {
    __syncthreads();
    if (threadIdx.x == 0) {
        unsigned s0 = atomicAdd(&g_sense[id], 0u);
        __threadfence();
        unsigned t = atomicAdd(&g_barr[id], 1u);
        if (t == total - 1u) {
            g_barr[id] = 0u;
            __threadfence();
            atomicAdd(&g_sense[id], 1u);
        } else {
            while (atomicAdd(&g_sense[id], 0u) == s0) __nanosleep(64);
        }
        __threadfence();
    }
    __syncthreads();
}

// ---------------- helpers ----------------------------------------------------
__device__ __forceinline__ uint32_t smem_u32(const void* p) {
    uint32_t a;
    asm("{ .reg .u64 t; cvta.to.shared.u64 t, %1; cvt.u32.u64 %0, t; }"
        : "=r"(a) : "l"(p));
    return a;
}
__device__ __forceinline__ uint32_t tf32_rna(float x) {
    uint32_t r;
    asm("cvt.rna.tf32.f32 %0, %1;" : "=r"(r) : "f"(x));
    return r;
}
__device__ __forceinline__ void mma_tf32(float* c, uint32_t a0, uint32_t a1,
                                         uint32_t a2, uint32_t a3,
                                         uint32_t b0, uint32_t b1) {
    asm volatile(
        "mma.sync.aligned.m16n8k8.row.col.f32.tf32.tf32.f32 "
        "{%0,%1,%2,%3}, {%4,%5,%6,%7}, {%8,%9}, {%0,%1,%2,%3};"
        : "+f"(c[0]), "+f"(c[1]), "+f"(c[2]), "+f"(c[3])
        : "r"(a0), "r"(a1), "r"(a2), "r"(a3), "r"(b0), "r"(b1));
}
__device__ __forceinline__ void cp16(uint32_t dst, const void* src) {
    asm volatile("cp.async.cg.shared.global [%0], [%1], 16;"
                 :: "r"(dst), "l"(src));
}
__device__ __forceinline__ void ldsm4(uint32_t& r0, uint32_t& r1, uint32_t& r2,
                                      uint32_t& r3, uint32_t addr) {
    asm volatile("ldmatrix.sync.aligned.m8n8.x4.shared.b16 {%0,%1,%2,%3}, [%4];"
                 : "=r"(r0), "=r"(r1), "=r"(r2), "=r"(r3) : "r"(addr));
}

// ---------------- GEMM tile device function ---------------------------------
// C[m0:+128, n0:+128] = A[M,K]*B[N,K]^T + bias. K = nchunk*16.
// 4-stage cp.async pipeline, one __syncthreads per chunk, exact tail waits.
#define NSTAGE 4
#define STG_B 20480                 // bytes per stage (A 10240 + B 10240)
#define DYN_SMEM (NSTAGE * STG_B)   // 81920

__device__ __noinline__ void gemm_tile(
    const float* __restrict__ A, const float* __restrict__ B,
    const float* __restrict__ bias, float* __restrict__ C,
    int lda, int ldb, int ldc, int nchunk, int split,
    int m0, int n0, float* dyn)
{
    __shared__ float bias_s[128];
    const int tid = threadIdx.x;
    const int wid = tid >> 5, lane = tid & 31;
    const int g = lane >> 2, tg = lane & 3;
    const int wm = wid >> 2, wn = wid & 3;
    const int lr = lane & 7, lq = lane >> 3;

    __syncthreads();   // smem reuse guard across calls
    if (tid < 128) bias_s[tid] = bias ? bias[n0 + tid] : 0.f;

    const uint32_t smem_base = smem_u32(dyn);
    const uint32_t a_off = (uint32_t)(((wm * 64 + (lq & 1) * 8 + lr) * 20 +
                                      (lq >> 1) * 4) * 4);
    const uint32_t b_off = (uint32_t)((2560 + (wn * 32 + (lq >> 1) * 8 + lr) * 20 +
                                      (lq & 1) * 4) * 4);
    const int lr0 = tid >> 2,          lk0 = tid & 3;
    const int lr1 = (tid + 256) >> 2,  lk1 = (tid + 256) & 3;

    auto load_chunk = [&](int c, int s) {
        const uint32_t sa = smem_base + s * STG_B;
        const uint32_t sb = sa + 10240;
        const float* Ag = A + (size_t)m0 * lda + c * 16;
        const float* Bg = B + (size_t)n0 * ldb + c * 16;
        cp16(sa + (lr0 * 20 + lk0 * 4) * 4, Ag + (size_t)lr0 * lda + lk0 * 4);
        cp16(sa + (lr1 * 20 + lk1 * 4) * 4, Ag + (size_t)lr1 * lda + lk1 * 4);
        cp16(sb + (lr0 * 20 + lk0 * 4) * 4, Bg + (size_t)lr0 * ldb + lk0 * 4);
        cp16(sb + (lr1 * 20 + lk1 * 4) * 4, Bg + (size_t)lr1 * ldb + lk1 * 4);
        asm volatile("cp.async.commit_group;" ::: "memory");
    };

    float acc[4][4][4];
#pragma unroll
    for (int mt = 0; mt < 4; mt++)
#pragma unroll
        for (int nt = 0; nt < 4; nt++)
#pragma unroll
            for (int q = 0; q < 4; q++) acc[mt][nt][q] = 0.f;

    load_chunk(0, 0); load_chunk(1, 1); load_chunk(2, 2);

    for (int t = 0; t < nchunk; t++) {
        if (t < nchunk - 2)
            asm volatile("cp.async.wait_group 2;" ::: "memory");
        else if (t == nchunk - 2)
            asm volatile("cp.async.wait_group 1;" ::: "memory");
        else
            asm volatile("cp.async.wait_group 0;" ::: "memory");
        __syncthreads();
        if (t + 3 < nchunk) load_chunk(t + 3, (t + 3) & 3);

        const uint32_t sbase = smem_base + (t & 3) * STG_B;
        const uint32_t abase = sbase + a_off;
        const uint32_t bbase = sbase + b_off;

#pragma unroll
        for (int ks = 0; ks < 2; ks++) {
            uint32_t au[4][4], bu[4][2];
#pragma unroll
            for (int mt = 0; mt < 4; mt++)
                ldsm4(au[mt][0], au[mt][1], au[mt][2], au[mt][3],
                      abase + mt * 1280 + ks * 32);
#pragma unroll
            for (int j = 0; j < 2; j++)
                ldsm4(bu[2 * j][0], bu[2 * j][1], bu[2 * j + 1][0],
                      bu[2 * j + 1][1], bbase + j * 1280 + ks * 32);

            if (!split) {
#pragma unroll
                for (int mt = 0; mt < 4; mt++)
#pragma unroll
                    for (int nt = 0; nt < 4; nt++)
                        mma_tf32(acc[mt][nt], au[mt][0], au[mt][1], au[mt][2],
                                 au[mt][3], bu[nt][0], bu[nt][1]);
            } else {
                uint32_t bh[4][2], bl[4][2];
#pragma unroll
                for (int nt = 0; nt < 4; nt++)
#pragma unroll
                    for (int q = 0; q < 2; q++) {
                        float v = __uint_as_float(bu[nt][q]);
                        uint32_t hi = tf32_rna(v);
                        bh[nt][q] = hi;
                        bl[nt][q] = tf32_rna(v - __uint_as_float(hi));
                    }
#pragma unroll
                for (int mt = 0; mt < 4; mt++) {
                    uint32_t ah[4], al[4];
#pragma unroll
                    for (int q = 0; q < 4; q++) {
                        float v = __uint_as_float(au[mt][q]);
                        ah[q] = tf32_rna(v);
                        al[q] = tf32_rna(v - __uint_as_float(ah[q]));
                    }
#pragma unroll
                    for (int nt = 0; nt < 4; nt++) {
                        mma_tf32(acc[mt][nt], al[0], al[1], al[2], al[3],
                                 bh[nt][0], bh[nt][1]);
                        mma_tf32(acc[mt][nt], ah[0], ah[1], ah[2], ah[3],
                                 bl[nt][0], bl[nt][1]);
                        mma_tf32(acc[mt][nt], ah[0], ah[1], ah[2], ah[3],
                                 bh[nt][0], bh[nt][1]);
                    }
                }
            }
        }
    }

#pragma unroll
    for (int mt = 0; mt < 4; mt++) {
        const int row = m0 + wm * 64 + mt * 16 + g;
        float* Cr0 = C + (size_t)row * ldc + n0;
        float* Cr1 = Cr0 + 8 * ldc;
#pragma unroll
        for (int nt = 0; nt < 4; nt++) {
            const int col = wn * 32 + nt * 8 + tg * 2;
            float2 v0 = make_float2(acc[mt][nt][0] + bias_s[col],
                                    acc[mt][nt][1] + bias_s[col + 1]);
            float2 v1 = make_float2(acc[mt][nt][2] + bias_s[col],
                                    acc[mt][nt][3] + bias_s[col + 1]);
            *(float2*)(Cr0 + col) = v0;
            *(float2*)(Cr1 + col) = v1;
        }
    }
}

// ---------------- L1: prep (transpose + repack) -> bar -> u split-K x4 ------
__global__ __launch_bounds__(256, 2) void k_umega(
    const float* __restrict__ attn_W, const float* __restrict__ pre_W,
    const float* __restrict__ hL1)
{
    extern __shared__ float dyn[];
    __shared__ float tsh[32][33];
    const int c = blockIdx.x, tid = threadIdx.x;
    const int tx = tid & 31, ty = tid >> 5;

#pragma unroll
    for (int i = 0; i < 8; i++) {
        const int tt = c + i * 128;
        const int bx = tt & 31, by = tt >> 5;
        __syncthreads();
#pragma unroll
        for (int j = 0; j < 32; j += 8)
            tsh[ty + j][tx] = attn_W[(size_t)(by * 32 + ty + j) * NH + bx * 32 + tx];
        __syncthreads();
#pragma unroll
        for (int j = 0; j < 32; j += 8)
            g_Wt[(size_t)(bx * 32 + ty + j) * NH + by * 32 + tx] = tsh[tx][ty + j];
    }
#pragma unroll
    for (int r = 0; r < 8; r++) {
        const int n = c * 8 + r;
        for (int k = tid; k < CAT_LD; k += 256)
            g_preW[(size_t)n * CAT_LD + k] =
                (k < NH + NM) ? pre_W[(size_t)n * (NH + NM) + k] : 0.f;
    }
    gbar(0, 128);

    const int s = c >> 5, rem = c & 31;
    const int n0 = (rem & 7) * 128, m0 = (rem >> 3) * 128;
    gemm_tile(hL1 + s * 256, g_Wt + s * 256, nullptr,
              g_upart + (size_t)s * NBNH, NH, NH, NH, 16, 1, m0, n0, dyn);
}

__device__ __forceinline__ float warp_sum(float v) {
#pragma unroll
    for (int o = 16; o; o >>= 1) v += __shfl_xor_sync(0xffffffffu, v, o);
    return v;
}

// ---------------- L2: fused attention (u-reduce + online softmax) -----------
__global__ __launch_bounds__(256, 3) void attn_fused(
    const float* __restrict__ enc, const float* __restrict__ motion,
    float* __restrict__ attn_out)
{
    const int b = blockIdx.x;
    const int tid = threadIdx.x;
    const int lane = tid & 31, w = tid >> 5;

    __shared__ float e_raw[NS];
    __shared__ float warp_m[8], warp_z[8];
    __shared__ __align__(16) float ur_s[NH];
    __shared__ __align__(16) float ctxs[8 * NH];

    {
        const float4* p0 = (const float4*)(g_upart + (size_t)b * NH);
        const float4* p1 = (const float4*)(g_upart + (size_t)NBNH + (size_t)b * NH);
        const float4* p2 = (const float4*)(g_upart + 2 * (size_t)NBNH + (size_t)b * NH);
        const float4* p3 = (const float4*)(g_upart + 3 * (size_t)NBNH + (size_t)b * NH);
        float4 a = p0[tid], c = p1[tid], d = p2[tid], e = p3[tid];
        ((float4*)ur_s)[tid] = make_float4(a.x + c.x + d.x + e.x,
                                           a.y + c.y + d.y + e.y,
                                           a.z + c.z + d.z + e.z,
                                           a.w + c.w + d.w + e.w);
    }
    __syncthreads();

    float4 cacc[8];
#pragma unroll
    for (int i = 0; i < 8; i++) cacc[i] = make_float4(0.f, 0.f, 0.f, 0.f);
    float m = -1e30f, Z = 0.f;
    const float4* u4 = (const float4*)ur_s;

#pragma unroll
    for (int si = 0; si < 8; si++) {
        const int s = w + si * 8;
        const float4* ep = (const float4*)(enc + ((size_t)s * NB + b) * NH);
        float4 row[8];
        float d = 0.f;
#pragma unroll
        for (int i = 0; i < 8; i++) {
            row[i] = ep[i * 32 + lane];
            float4 uv = u4[i * 32 + lane];
            d = fmaf(row[i].x, uv.x, d);
            d = fmaf(row[i].y, uv.y, d);
            d = fmaf(row[i].z, uv.z, d);
            d = fmaf(row[i].w, uv.w, d);
        }
        d = warp_sum(d);
        if (lane == 0) e_raw[s] = d;
        const float mn = fmaxf(m, d);
        const float scale = __expf(m - mn);
        const float wgt = __expf(d - mn);
        Z = Z * scale + wgt;
#pragma unroll
        for (int i = 0; i < 8; i++) {
            cacc[i].x = fmaf(cacc[i].x, scale, wgt * row[i].x);
            cacc[i].y = fmaf(cacc[i].y, scale, wgt * row[i].y);
            cacc[i].z = fmaf(cacc[i].z, scale, wgt * row[i].z);
            cacc[i].w = fmaf(cacc[i].w, scale, wgt * row[i].w);
        }
        m = mn;
    }

    if (lane == 0) { warp_m[w] = m; warp_z[w] = Z; }
    float4* cs = (float4*)(ctxs + w * NH);
#pragma unroll
    for (int i = 0; i < 8; i++) cs[i * 32 + lane] = cacc[i];
    __syncthreads();

    float gm = warp_m[0];
#pragma unroll
    for (int ww = 1; ww < 8; ww++) gm = fmaxf(gm, warp_m[ww]);
    float gZ = 0.f;
#pragma unroll
    for (int ww = 0; ww < 8; ww++) gZ += warp_z[ww] * __expf(warp_m[ww] - gm);
    const float invZ = 1.f / gZ;

    if (tid < NS) attn_out[(size_t)b * NS + tid] = __expf(e_raw[tid] - gm) * invZ;
    if (tid < NM) g_cat[(size_t)b * CAT_LD + tid] = motion[(size_t)b * NM + tid];
    if (tid < CAT_LD - NH - NM)
        g_cat[(size_t)b * CAT_LD + NH + NM + tid] = 0.f;

    float4 a = make_float4(0.f, 0.f, 0.f, 0.f);
#pragma unroll
    for (int ww = 0; ww < 8; ww++) {
        const float sc = __expf(warp_m[ww] - gm);
        float4 v = *(const float4*)&ctxs[ww * NH + tid * 4];
        a.x = fmaf(v.x, sc, a.x);
        a.y = fmaf(v.y, sc, a.y);
        a.z = fmaf(v.z, sc, a.z);
        a.w = fmaf(v.w, sc, a.w);
    }
    float* cp = g_cat + (size_t)b * CAT_LD + NM + tid * 4;
    *(float2*)cp       = make_float2(a.x * invZ, a.y * invZ);
    *(float2*)(cp + 2) = make_float2(a.z * invZ, a.w * invZ);
}

// ---------------- L3: [gh0/2 + pre/6] -> xreduce -> gi0/2 -> gate0 ----------
__global__ __launch_bounds__(256, 2) void k_mega0(
    const float* __restrict__ hL0, const float* __restrict__ pre_b,
    const float* __restrict__ Whh0, const float* __restrict__ bhh0,
    const float* __restrict__ Wih0, const float* __restrict__ bih0,
    float* __restrict__ out_h0)
{
    extern __shared__ float dyn[];
    const int c = blockIdx.x, tid = threadIdx.x;

    {   // gh0 half-K tile
        const int n0 = (c % 24) * 128, m0 = ((c / 24) % 4) * 128, k = c / 96;
        gemm_tile(hL0 + k * 512, Whh0 + k * 512, k ? nullptr : bhh0,
                  k ? g_ghB : g_ghA, NH, NH, G3, 32, 0, m0, n0, dyn);
    }
    {   // pre sixth-K tile
        const int s = c / 32, rem = c % 32;
        const int n0 = (rem & 7) * 128, m0 = (rem >> 3) * 128;
        gemm_tile(g_cat + s * 176, g_preW + s * 176, s ? nullptr : pre_b,
                  g_xpart + (size_t)s * NBNH, CAT_LD, CAT_LD, NH, 11, 0,
                  m0, n0, dyn);
    }
    gbar(1, 192);

    for (int i = c * 256 + tid; i < NBNH / 4; i += 192 * 256) {
        float4 v = ((const float4*)g_xpart)[i];
#pragma unroll
        for (int s = 1; s < 6; s++) {
            float4 ww = ((const float4*)(g_xpart + (size_t)s * NBNH))[i];
            v.x += ww.x; v.y += ww.y; v.z += ww.z; v.w += ww.w;
        }
        ((float4*)g_x0)[i] = v;
    }
    gbar(2, 192);

    {   // gi0 half-K tile
        const int n0 = (c % 24) * 128, m0 = ((c / 24) % 4) * 128, k = c / 96;
        gemm_tile(g_x0 + k * 512, Wih0 + k * 512, k ? nullptr : bih0,
                  k ? g_giB : g_giA, NH, NH, G3, 32, 0, m0, n0, dyn);
    }
    gbar(3, 192);

    for (int idx = c * 256 + tid; idx < NBNH; idx += 192 * 256) {
        const int b = idx >> 10, n = idx & (NH - 1);
        const size_t o = (size_t)b * G3 + n;
        float ir = g_giA[o] + g_giB[o];
        float iz = g_giA[o + NH] + g_giB[o + NH];
        float inn = g_giA[o + 2 * NH] + g_giB[o + 2 * NH];
        float hr = g_ghA[o] + g_ghB[o];
        float hz = g_ghA[o + NH] + g_ghB[o + NH];
        float hn = g_ghA[o + 2 * NH] + g_ghB[o + 2 * NH];
        float r = 1.f / (1.f + expf(-(ir + hr)));
        float z = 1.f / (1.f + expf(-(iz + hz)));
        float nn = tanhf(inn + r * hn);
        out_h0[idx] = (1.f - z) * nn + z * hL0[idx];
    }
}

// ---------------- L4: [gi1/2 + gh1/2] -> gate1 + post -----------------------
__global__ __launch_bounds__(256, 2) void k_mega1(
    const float* __restrict__ hL1, const float* __restrict__ h0,
    const float* __restrict__ Wih1, const float* __restrict__ bih1,
    const float* __restrict__ Whh1, const float* __restrict__ bhh1,
    float* __restrict__ out_h1, const float* __restrict__ postW,
    const float* __restrict__ postb, float* __restrict__ out_out)
{
    extern __shared__ float dyn[];
    __shared__ float red[10][8];
    const int c = blockIdx.x, tid = threadIdx.x;
    const int lane = tid & 31, w = tid >> 5;

    {
        const int n0 = (c % 24) * 128, m0 = ((c / 24) % 4) * 128, k = c / 96;
        gemm_tile(h0 + k * 512, Wih1 + k * 512, k ? nullptr : bih1,
                  k ? g_giB : g_giA, NH, NH, G3, 32, 0, m0, n0, dyn);
        gemm_tile(hL1 + k * 512, Whh1 + k * 512, k ? nullptr : bhh1,
                  k ? g_ghB : g_ghA, NH, NH, G3, 32, 0, m0, n0, dyn);
    }
    gbar(4, 192);

    for (int b = c; b < NB; b += 192) {
        float hv[4];
#pragma unroll
        for (int q = 0; q < 4; q++) {
            const int n = tid * 4 + q;
            const size_t o = (size_t)b * G3 + n;
            float ir = g_giA[o] + g_giB[o];
            float iz = g_giA[o + NH] + g_giB[o + NH];
            float inn = g_giA[o + 2 * NH] + g_giB[o + 2 * NH];
            float hr = g_ghA[o] + g_ghB[o];
            float hz = g_ghA[o + NH] + g_ghB[o + NH];
            float hn = g_ghA[o + 2 * NH] + g_ghB[o + 2 * NH];
            float r = 1.f / (1.f + expf(-(ir + hr)));
            float z = 1.f / (1.f + expf(-(iz + hz)));
            float nn = tanhf(inn + r * hn);
            hv[q] = (1.f - z) * nn + z * hL1[(size_t)b * NH + n];
        }
        *(float4*)(out_h1 + (size_t)b * NH + tid * 4) =
            make_float4(hv[0], hv[1], hv[2], hv[3]);

        float acc[10];
#pragma unroll
        for (int o = 0; o < 10; o++) {
            const float4 wv = *(const float4*)(postW + (size_t)o * NH + tid * 4);
            acc[o] = hv[0] * wv.x + hv[1] * wv.y + hv[2] * wv.z + hv[3] * wv.w;
        }
#pragma unroll
        for (int o = 0; o < 10; o++) {
            float v = warp_sum(acc[o]);
            if (lane == 0) red[o][w] = v;
        }
        __syncthreads();
        if (tid < 10) {
            float s = 0.f;
#pragma unroll
            for (int ww = 0; ww < 8; ww++) s += red[tid][ww];
            out_out[(size_t)b * 10 + tid] = s + postb[tid];
        }
        __syncthreads();
    }
}

// ---------------- host launch ------------------------------------------------
extern "C" void kernel_launch(void* const* d_in, const int* in_sizes, int n_in,
                              void* d_out, int out_size)
{
    const float* motion      = (const float*)d_in[0];
    const float* last_hidden = (const float*)d_in[1];
    const float* enc         = (const float*)d_in[2];
    const float* attn_W      = (const float*)d_in[3];
    /* d_in[4] = attn_b: unused (softmax shift-invariant) */
    const float* pre_W  = (const float*)d_in[5];
    const float* pre_b  = (const float*)d_in[6];
    const float* Wih0   = (const float*)d_in[7];
    const float* Whh0   = (const float*)d_in[8];
    const float* bih0   = (const float*)d_in[9];
    const float* bhh0   = (const float*)d_in[10];
    const float* Wih1   = (const float*)d_in[11];
    const float* Whh1   = (const float*)d_in[12];
    const float* bih1   = (const float*)d_in[13];
    const float* bhh1   = (const float*)d_in[14];
    const float* post_W = (const float*)d_in[15];
    const float* post_b = (const float*)d_in[16];

    float* out        = (float*)d_out;
    float* out_output = out;
    float* out_h0     = out + NB * 10;
    float* out_h1     = out + NB * 10 + NBNH;
    float* out_attn   = out + NB * 10 + 2 * NBNH;

    const float* hL0 = last_hidden;
    const float* hL1 = last_hidden + NBNH;

    cudaFuncSetAttribute(k_umega, cudaFuncAttributeMaxDynamicSharedMemorySize,
                         DYN_SMEM);
    cudaFuncSetAttribute(k_mega0, cudaFuncAttributeMaxDynamicSharedMemorySize,
                         DYN_SMEM);
    cudaFuncSetAttribute(k_mega1, cudaFuncAttributeMaxDynamicSharedMemorySize,
                         DYN_SMEM);

    k_umega<<<128, 256, DYN_SMEM>>>(attn_W, pre_W, hL1);
    attn_fused<<<NB, 256>>>(enc, motion, out_attn);
    k_mega0<<<192, 256, DYN_SMEM>>>(hL0, pre_b, Whh0, bhh0, Wih0, bih0, out_h0);
    k_mega1<<<192, 256, DYN_SMEM>>>(hL1, out_h0, Wih1, bih1, Whh1, bhh1,
                                    out_h1, post_W, post_b, out_output);
}

// round 9
// speedup vs baseline: 1.3433x; 1.3433x over previous
#include <cuda_runtime.h>
#include <math.h>
#include <stdint.h>

#define NB 512
#define NH 1024
#define NS 64
#define NM 10
#define CAT_LD 1056
#define NBNH (NB * NH)
#define G3 (3 * NH)
#define NJOBS 4

// ---------------- scratch (device globals) ----------------------------------
__device__ __align__(1024) float g_Wt[NH * NH];
__device__ __align__(1024) float g_preW[NH * CAT_LD];
__device__ __align__(1024) float g_upart[4 * NBNH];
__device__ __align__(1024) float g_cat[NB * CAT_LD];
__device__ __align__(1024) float g_xpart[3 * NBNH];
__device__ __align__(1024) float g_x0[NBNH];
__device__ __align__(1024) float g_gi0[NB * G3];
__device__ __align__(1024) float g_gh0[NB * G3];
__device__ __align__(1024) float g_gh1[NB * G3];
__device__ __align__(1024) float g_gi1A[NB * G3];
__device__ __align__(1024) float g_gi1B[NB * G3];

struct Jobs {
    const float* A[NJOBS]; const float* B[NJOBS];
    const float* bias[NJOBS]; float* C[NJOBS];
    int lda[NJOBS], ldb[NJOBS], ldc[NJOBS], nchunk[NJOBS], nx[NJOBS], split[NJOBS];
};

// ---------------- helpers ----------------------------------------------------
__device__ __forceinline__ uint32_t smem_u32(const void* p) {
    uint32_t a;
    asm("{ .reg .u64 t; cvta.to.shared.u64 t, %1; cvt.u32.u64 %0, t; }"
        : "=r"(a) : "l"(p));
    return a;
}
__device__ __forceinline__ uint32_t tf32_rna(float x) {
    uint32_t r;
    asm("cvt.rna.tf32.f32 %0, %1;" : "=r"(r) : "f"(x));
    return r;
}
__device__ __forceinline__ void mma_tf32(float* c, uint32_t a0, uint32_t a1,
                                         uint32_t a2, uint32_t a3,
                                         uint32_t b0, uint32_t b1) {
    asm volatile(
        "mma.sync.aligned.m16n8k8.row.col.f32.tf32.tf32.f32 "
        "{%0,%1,%2,%3}, {%4,%5,%6,%7}, {%8,%9}, {%0,%1,%2,%3};"
        : "+f"(c[0]), "+f"(c[1]), "+f"(c[2]), "+f"(c[3])
        : "r"(a0), "r"(a1), "r"(a2), "r"(a3), "r"(b0), "r"(b1));
}
__device__ __forceinline__ void cp16(uint32_t dst, const void* src) {
    asm volatile("cp.async.cg.shared.global [%0], [%1], 16;"
                 :: "r"(dst), "l"(src));
}
__device__ __forceinline__ void ldsm4(uint32_t& r0, uint32_t& r1, uint32_t& r2,
                                      uint32_t& r3, uint32_t addr) {
    asm volatile("ldmatrix.sync.aligned.m8n8.x4.shared.b16 {%0,%1,%2,%3}, [%4];"
                 : "=r"(r0), "=r"(r1), "=r"(r2), "=r"(r3) : "r"(addr));
}

// ---------------- tf32 warp-MMA GEMM (job-table batched) --------------------
// 4-stage cp.async pipeline, ONE __syncthreads per chunk, exact tail waits.
#define NSTAGE 4
#define STG_B 20480
#define DYN_SMEM (NSTAGE * STG_B)   // 81920

__global__ __launch_bounds__(256, 2) void gemm_mma(Jobs jobs)
{
    const int z = blockIdx.z;
    if (blockIdx.x >= jobs.nx[z]) return;

    extern __shared__ float dyn[];
    __shared__ float bias_s[128];

    const float* A = jobs.A[z];
    const float* B = jobs.B[z];
    const float* bias = jobs.bias[z];
    float* C = jobs.C[z];
    const int lda = jobs.lda[z], ldb = jobs.ldb[z], ldc = jobs.ldc[z];
    const int nchunk = jobs.nchunk[z], split = jobs.split[z];

    const int tid = threadIdx.x;
    const int wid = tid >> 5, lane = tid & 31;
    const int g = lane >> 2, tg = lane & 3;
    const int wm = wid >> 2, wn = wid & 3;
    const int lr = lane & 7, lq = lane >> 3;
    const int n0 = blockIdx.x * 128;
    const int m0 = blockIdx.y * 128;

    if (tid < 128) bias_s[tid] = bias ? bias[n0 + tid] : 0.f;

    const uint32_t smem_base = smem_u32(dyn);
    const uint32_t a_off = (uint32_t)(((wm * 64 + (lq & 1) * 8 + lr) * 20 +
                                      (lq >> 1) * 4) * 4);
    const uint32_t b_off = (uint32_t)((2560 + (wn * 32 + (lq >> 1) * 8 + lr) * 20 +
                                      (lq & 1) * 4) * 4);
    const int lr0 = tid >> 2,          lk0 = tid & 3;
    const int lr1 = (tid + 256) >> 2,  lk1 = (tid + 256) & 3;

    auto load_chunk = [&](int c, int s) {
        const uint32_t sa = smem_base + s * STG_B;
        const uint32_t sb = sa + 10240;
        const float* Ag = A + (size_t)m0 * lda + c * 16;
        const float* Bg = B + (size_t)n0 * ldb + c * 16;
        cp16(sa + (lr0 * 20 + lk0 * 4) * 4, Ag + (size_t)lr0 * lda + lk0 * 4);
        cp16(sa + (lr1 * 20 + lk1 * 4) * 4, Ag + (size_t)lr1 * lda + lk1 * 4);
        cp16(sb + (lr0 * 20 + lk0 * 4) * 4, Bg + (size_t)lr0 * ldb + lk0 * 4);
        cp16(sb + (lr1 * 20 + lk1 * 4) * 4, Bg + (size_t)lr1 * ldb + lk1 * 4);
        asm volatile("cp.async.commit_group;" ::: "memory");
    };

    float acc[4][4][4];
#pragma unroll
    for (int mt = 0; mt < 4; mt++)
#pragma unroll
        for (int nt = 0; nt < 4; nt++)
#pragma unroll
            for (int q = 0; q < 4; q++) acc[mt][nt][q] = 0.f;

    load_chunk(0, 0); load_chunk(1, 1); load_chunk(2, 2);

    for (int t = 0; t < nchunk; t++) {
        if (t < nchunk - 2)
            asm volatile("cp.async.wait_group 2;" ::: "memory");
        else if (t == nchunk - 2)
            asm volatile("cp.async.wait_group 1;" ::: "memory");
        else
            asm volatile("cp.async.wait_group 0;" ::: "memory");
        __syncthreads();
        if (t + 3 < nchunk) load_chunk(t + 3, (t + 3) & 3);

        const uint32_t sbase = smem_base + (t & 3) * STG_B;
        const uint32_t abase = sbase + a_off;
        const uint32_t bbase = sbase + b_off;

#pragma unroll
        for (int ks = 0; ks < 2; ks++) {
            uint32_t au[4][4], bu[4][2];
#pragma unroll
            for (int mt = 0; mt < 4; mt++)
                ldsm4(au[mt][0], au[mt][1], au[mt][2], au[mt][3],
                      abase + mt * 1280 + ks * 32);
#pragma unroll
            for (int j = 0; j < 2; j++)
                ldsm4(bu[2 * j][0], bu[2 * j][1], bu[2 * j + 1][0],
                      bu[2 * j + 1][1], bbase + j * 1280 + ks * 32);

            if (!split) {
#pragma unroll
                for (int mt = 0; mt < 4; mt++)
#pragma unroll
                    for (int nt = 0; nt < 4; nt++)
                        mma_tf32(acc[mt][nt], au[mt][0], au[mt][1], au[mt][2],
                                 au[mt][3], bu[nt][0], bu[nt][1]);
            } else {
                uint32_t bh[4][2], bl[4][2];
#pragma unroll
                for (int nt = 0; nt < 4; nt++)
#pragma unroll
                    for (int q = 0; q < 2; q++) {
                        float v = __uint_as_float(bu[nt][q]);
                        uint32_t hi = tf32_rna(v);
                        bh[nt][q] = hi;
                        bl[nt][q] = tf32_rna(v - __uint_as_float(hi));
                    }
#pragma unroll
                for (int mt = 0; mt < 4; mt++) {
                    uint32_t ah[4], al[4];
#pragma unroll
                    for (int q = 0; q < 4; q++) {
                        float v = __uint_as_float(au[mt][q]);
                        ah[q] = tf32_rna(v);
                        al[q] = tf32_rna(v - __uint_as_float(ah[q]));
                    }
#pragma unroll
                    for (int nt = 0; nt < 4; nt++) {
                        mma_tf32(acc[mt][nt], al[0], al[1], al[2], al[3],
                                 bh[nt][0], bh[nt][1]);
                        mma_tf32(acc[mt][nt], ah[0], ah[1], ah[2], ah[3],
                                 bl[nt][0], bl[nt][1]);
                        mma_tf32(acc[mt][nt], ah[0], ah[1], ah[2], ah[3],
                                 bh[nt][0], bh[nt][1]);
                    }
                }
            }
        }
    }

#pragma unroll
    for (int mt = 0; mt < 4; mt++) {
        const int row = m0 + wm * 64 + mt * 16 + g;
        float* Cr0 = C + (size_t)row * ldc + n0;
        float* Cr1 = Cr0 + 8 * ldc;
#pragma unroll
        for (int nt = 0; nt < 4; nt++) {
            const int col = wn * 32 + nt * 8 + tg * 2;
            float2 v0 = make_float2(acc[mt][nt][0] + bias_s[col],
                                    acc[mt][nt][1] + bias_s[col + 1]);
            float2 v1 = make_float2(acc[mt][nt][2] + bias_s[col],
                                    acc[mt][nt][3] + bias_s[col + 1]);
            *(float2*)(Cr0 + col) = v0;
            *(float2*)(Cr1 + col) = v1;
        }
    }
}

// ---------------- prep: attn_W transpose + pre_W repack ---------------------
__global__ __launch_bounds__(256) void prep_kernel(
    const float* __restrict__ attn_W, float* __restrict__ Wt,
    const float* __restrict__ pre_W, float* __restrict__ preW)
{
    if (blockIdx.y < 32) {
        __shared__ float t[32][33];
        const int tx = threadIdx.x & 31, ty = threadIdx.x >> 5;
        int x = blockIdx.x * 32 + tx;
        int y0 = blockIdx.y * 32 + ty;
#pragma unroll
        for (int j = 0; j < 32; j += 8)
            t[ty + j][tx] = attn_W[(size_t)(y0 + j) * NH + x];
        __syncthreads();
        x = blockIdx.y * 32 + tx;
        y0 = blockIdx.x * 32 + ty;
#pragma unroll
        for (int j = 0; j < 32; j += 8)
            Wt[(size_t)(y0 + j) * NH + x] = t[tx][ty + j];
    } else {
        const int n = (blockIdx.y - 32) * 32 + blockIdx.x;
        for (int k = threadIdx.x; k < CAT_LD; k += 256)
            preW[(size_t)n * CAT_LD + k] =
                (k < NH + NM) ? pre_W[(size_t)n * (NH + NM) + k] : 0.f;
    }
}

__device__ __forceinline__ float warp_sum(float v) {
#pragma unroll
    for (int o = 16; o; o >>= 1) v += __shfl_xor_sync(0xffffffffu, v, o);
    return v;
}

// ---------------- fused attention: u-reduce + online softmax + context ------
__global__ __launch_bounds__(256, 3) void attn_fused(
    const float* __restrict__ enc, const float* __restrict__ upart,
    const float* __restrict__ motion, float* __restrict__ attn_out,
    float* __restrict__ cat)
{
    const int b = blockIdx.x;
    const int tid = threadIdx.x;
    const int lane = tid & 31, w = tid >> 5;

    __shared__ float e_raw[NS];
    __shared__ float warp_m[8], warp_z[8];
    __shared__ __align__(16) float ur_s[NH];
    __shared__ __align__(16) float ctxs[8 * NH];

    {
        const float4* p0 = (const float4*)(upart + (size_t)b * NH);
        const float4* p1 = (const float4*)(upart + (size_t)NBNH + (size_t)b * NH);
        const float4* p2 = (const float4*)(upart + 2 * (size_t)NBNH + (size_t)b * NH);
        const float4* p3 = (const float4*)(upart + 3 * (size_t)NBNH + (size_t)b * NH);
        float4 a = p0[tid], c = p1[tid], d = p2[tid], e = p3[tid];
        ((float4*)ur_s)[tid] = make_float4(a.x + c.x + d.x + e.x,
                                           a.y + c.y + d.y + e.y,
                                           a.z + c.z + d.z + e.z,
                                           a.w + c.w + d.w + e.w);
    }
    __syncthreads();

    float4 cacc[8];
#pragma unroll
    for (int i = 0; i < 8; i++) cacc[i] = make_float4(0.f, 0.f, 0.f, 0.f);
    float m = -1e30f, Z = 0.f;
    const float4* u4 = (const float4*)ur_s;

#pragma unroll
    for (int si = 0; si < 8; si++) {
        const int s = w + si * 8;
        const float4* ep = (const float4*)(enc + ((size_t)s * NB + b) * NH);
        float4 row[8];
        float d = 0.f;
#pragma unroll
        for (int i = 0; i < 8; i++) {
            row[i] = ep[i * 32 + lane];
            float4 uv = u4[i * 32 + lane];
            d = fmaf(row[i].x, uv.x, d);
            d = fmaf(row[i].y, uv.y, d);
            d = fmaf(row[i].z, uv.z, d);
            d = fmaf(row[i].w, uv.w, d);
        }
        d = warp_sum(d);
        if (lane == 0) e_raw[s] = d;
        const float mn = fmaxf(m, d);
        const float scale = __expf(m - mn);
        const float wgt = __expf(d - mn);
        Z = Z * scale + wgt;
#pragma unroll
        for (int i = 0; i < 8; i++) {
            cacc[i].x = fmaf(cacc[i].x, scale, wgt * row[i].x);
            cacc[i].y = fmaf(cacc[i].y, scale, wgt * row[i].y);
            cacc[i].z = fmaf(cacc[i].z, scale, wgt * row[i].z);
            cacc[i].w = fmaf(cacc[i].w, scale, wgt * row[i].w);
        }
        m = mn;
    }

    if (lane == 0) { warp_m[w] = m; warp_z[w] = Z; }
    float4* cs = (float4*)(ctxs + w * NH);
#pragma unroll
    for (int i = 0; i < 8; i++) cs[i * 32 + lane] = cacc[i];
    __syncthreads();

    float gm = warp_m[0];
#pragma unroll
    for (int ww = 1; ww < 8; ww++) gm = fmaxf(gm, warp_m[ww]);
    float gZ = 0.f;
#pragma unroll
    for (int ww = 0; ww < 8; ww++) gZ += warp_z[ww] * __expf(warp_m[ww] - gm);
    const float invZ = 1.f / gZ;

    if (tid < NS) attn_out[(size_t)b * NS + tid] = __expf(e_raw[tid] - gm) * invZ;
    if (tid < NM) cat[(size_t)b * CAT_LD + tid] = motion[(size_t)b * NM + tid];
    if (tid < CAT_LD - NH - NM)
        cat[(size_t)b * CAT_LD + NH + NM + tid] = 0.f;

    float4 a = make_float4(0.f, 0.f, 0.f, 0.f);
#pragma unroll
    for (int ww = 0; ww < 8; ww++) {
        const float sc = __expf(warp_m[ww] - gm);
        float4 v = *(const float4*)&ctxs[ww * NH + tid * 4];
        a.x = fmaf(v.x, sc, a.x);
        a.y = fmaf(v.y, sc, a.y);
        a.z = fmaf(v.z, sc, a.z);
        a.w = fmaf(v.w, sc, a.w);
    }
    float* cp = cat + (size_t)b * CAT_LD + NM + tid * 4;
    *(float2*)cp       = make_float2(a.x * invZ, a.y * invZ);
    *(float2*)(cp + 2) = make_float2(a.z * invZ, a.w * invZ);
}

// ---------------- x0 split-K reduce (3 partials) ----------------------------
__global__ __launch_bounds__(256) void xreduce(const float* __restrict__ p,
                                               float* __restrict__ x0)
{
    const int i = (blockIdx.x * 256 + threadIdx.x) * 4;
    float4 a = *(const float4*)(p + i);
    float4 b = *(const float4*)(p + (size_t)NBNH + i);
    float4 c = *(const float4*)(p + 2 * (size_t)NBNH + i);
    *(float4*)(x0 + i) = make_float4(a.x + b.x + c.x, a.y + b.y + c.y,
                                     a.z + b.z + c.z, a.w + b.w + c.w);
}

// ---------------- GRU gate pointwise (layer 0) ------------------------------
__global__ __launch_bounds__(256) void gate_kernel(
    const float* __restrict__ gi, const float* __restrict__ gh,
    const float* __restrict__ hprev, float* __restrict__ out_h)
{
    const int idx = blockIdx.x * blockDim.x + threadIdx.x;
    const int b = idx >> 10, n = idx & (NH - 1);
    const float* gib = gi + (size_t)b * G3;
    const float* ghb = gh + (size_t)b * G3;
    float ir = gib[n], iz = gib[NH + n], inn = gib[2 * NH + n];
    float hr = ghb[n], hz = ghb[NH + n], hn = ghb[2 * NH + n];
    float r = 1.f / (1.f + expf(-(ir + hr)));
    float z = 1.f / (1.f + expf(-(iz + hz)));
    float nn = tanhf(inn + r * hn);
    out_h[idx] = (1.f - z) * nn + z * hprev[idx];
}

// ---------------- fused gate(layer 1, split-K gi) + post linear -------------
__global__ __launch_bounds__(256) void gatepost_kernel(
    const float* __restrict__ giA, const float* __restrict__ giB,
    const float* __restrict__ gh, const float* __restrict__ hprev,
    float* __restrict__ out_h, const float* __restrict__ W,
    const float* __restrict__ bias, float* __restrict__ out)
{
    const int b = blockIdx.x;
    const int tid = threadIdx.x;

    float hv[4];
#pragma unroll
    for (int q = 0; q < 4; q++) {
        const int n = tid * 4 + q;
        const size_t o = (size_t)b * G3 + n;
        float ir = giA[o] + giB[o];
        float iz = giA[o + NH] + giB[o + NH];
        float inn = giA[o + 2 * NH] + giB[o + 2 * NH];
        float hr = gh[o], hz = gh[o + NH], hn = gh[o + 2 * NH];
        float r = 1.f / (1.f + expf(-(ir + hr)));
        float z = 1.f / (1.f + expf(-(iz + hz)));
        float nn = tanhf(inn + r * hn);
        hv[q] = (1.f - z) * nn + z * hprev[(size_t)b * NH + n];
    }
    *(float4*)(out_h + (size_t)b * NH + tid * 4) =
        make_float4(hv[0], hv[1], hv[2], hv[3]);

    float acc[10];
#pragma unroll
    for (int o = 0; o < 10; o++) {
        const float4 wv = *(const float4*)(W + (size_t)o * NH + tid * 4);
        acc[o] = hv[0] * wv.x + hv[1] * wv.y + hv[2] * wv.z + hv[3] * wv.w;
    }
    __shared__ float red[10][8];
    const int lane = tid & 31, w = tid >> 5;
#pragma unroll
    for (int o = 0; o < 10; o++) {
        float v = warp_sum(acc[o]);
        if (lane == 0) red[o][w] = v;
    }
    __syncthreads();
    if (tid < 10) {
        float s = 0.f;
#pragma unroll
        for (int ww = 0; ww < 8; ww++) s += red[tid][ww];
        out[(size_t)b * 10 + tid] = s + bias[tid];
    }
}

// ---------------- host launch ------------------------------------------------
extern "C" void kernel_launch(void* const* d_in, const int* in_sizes, int n_in,
                              void* d_out, int out_size)
{
    const float* motion      = (const float*)d_in[0];
    const float* last_hidden = (const float*)d_in[1];
    const float* enc         = (const float*)d_in[2];
    const float* attn_W      = (const float*)d_in[3];
    /* d_in[4] = attn_b: unused (softmax shift-invariant) */
    const float* pre_W  = (const float*)d_in[5];
    const float* pre_b  = (const float*)d_in[6];
    const float* Wih0   = (const float*)d_in[7];
    const float* Whh0   = (const float*)d_in[8];
    const float* bih0   = (const float*)d_in[9];
    const float* bhh0   = (const float*)d_in[10];
    const float* Wih1   = (const float*)d_in[11];
    const float* Whh1   = (const float*)d_in[12];
    const float* bih1   = (const float*)d_in[13];
    const float* bhh1   = (const float*)d_in[14];
    const float* post_W = (const float*)d_in[15];
    const float* post_b = (const float*)d_in[16];

    float* out        = (float*)d_out;
    float* out_output = out;
    float* out_h0     = out + NB * 10;
    float* out_h1     = out + NB * 10 + NBNH;
    float* out_attn   = out + NB * 10 + 2 * NBNH;

    float *upart, *xpart, *cat, *x0, *gi0, *gh0, *gh1, *gi1A, *gi1B, *preW, *Wt;
    cudaGetSymbolAddress((void**)&upart, g_upart);
    cudaGetSymbolAddress((void**)&xpart, g_xpart);
    cudaGetSymbolAddress((void**)&cat,   g_cat);
    cudaGetSymbolAddress((void**)&x0,    g_x0);
    cudaGetSymbolAddress((void**)&gi0,   g_gi0);
    cudaGetSymbolAddress((void**)&gh0,   g_gh0);
    cudaGetSymbolAddress((void**)&gh1,   g_gh1);
    cudaGetSymbolAddress((void**)&gi1A,  g_gi1A);
    cudaGetSymbolAddress((void**)&gi1B,  g_gi1B);
    cudaGetSymbolAddress((void**)&preW,  g_preW);
    cudaGetSymbolAddress((void**)&Wt,    g_Wt);

    const float* hL0 = last_hidden;
    const float* hL1 = last_hidden + NBNH;

    cudaFuncSetAttribute(gemm_mma, cudaFuncAttributeMaxDynamicSharedMemorySize,
                         DYN_SMEM);

    // 1) prep (transpose + repack)
    prep_kernel<<<dim3(32, 64), 256>>>(attn_W, Wt, pre_W, preW);

    // 2) u split-K x4 alone (critical path start; gh moved later)
    {
        Jobs j = {};
        for (int s = 0; s < 4; s++) {
            j.A[s] = hL1 + s * 256;  j.B[s] = Wt + s * 256;
            j.bias[s] = nullptr;     j.C[s] = upart + (size_t)s * NBNH;
            j.lda[s] = NH; j.ldb[s] = NH; j.ldc[s] = NH;
            j.nchunk[s] = 16; j.nx[s] = 8; j.split[s] = 1;
        }
        gemm_mma<<<dim3(8, 4, 4), 256, DYN_SMEM>>>(j);
    }

    // 3) fused attention
    attn_fused<<<NB, 256>>>(enc, upart, motion, out_attn, cat);

    // 4) pre split-K x3
    {
        Jobs j = {};
        for (int s = 0; s < 3; s++) {
            j.A[s] = cat + s * 352;  j.B[s] = preW + s * 352;
            j.bias[s] = (s == 0) ? pre_b : nullptr;
            j.C[s] = xpart + (size_t)s * NBNH;
            j.lda[s] = CAT_LD; j.ldb[s] = CAT_LD; j.ldc[s] = NH;
            j.nchunk[s] = 22; j.nx[s] = 8; j.split[s] = 0;
        }
        gemm_mma<<<dim3(8, 4, 3), 256, DYN_SMEM>>>(j);
    }
    xreduce<<<NBNH / 1024, 256>>>(xpart, x0);

    // 5) BIG combo: gi0 + gh0 + gh1 — 288 identical 64-chunk CTAs = 1 wave
    {
        Jobs j = {};
        j.A[0] = x0;  j.B[0] = Wih0; j.bias[0] = bih0; j.C[0] = gi0;
        j.A[1] = hL0; j.B[1] = Whh0; j.bias[1] = bhh0; j.C[1] = gh0;
        j.A[2] = hL1; j.B[2] = Whh1; j.bias[2] = bhh1; j.C[2] = gh1;
        for (int s = 0; s < 3; s++) {
            j.lda[s] = NH; j.ldb[s] = NH; j.ldc[s] = G3;
            j.nchunk[s] = 64; j.nx[s] = 24; j.split[s] = 0;
        }
        gemm_mma<<<dim3(24, 4, 3), 256, DYN_SMEM>>>(j);
    }
    gate_kernel<<<NBNH / 256, 256>>>(gi0, gh0, hL0, out_h0);

    // 6) gi1 split-K x2 (192 CTAs)
    {
        Jobs j = {};
        for (int k = 0; k < 2; k++) {
            j.A[k] = out_h0 + k * 512; j.B[k] = Wih1 + k * 512;
            j.bias[k] = k ? nullptr : bih1;
            j.C[k] = k ? gi1B : gi1A;
            j.lda[k] = NH; j.ldb[k] = NH; j.ldc[k] = G3;
            j.nchunk[k] = 32; j.nx[k] = 24; j.split[k] = 0;
        }
        gemm_mma<<<dim3(24, 4, 2), 256, DYN_SMEM>>>(j);
    }
    gatepost_kernel<<<NB, 256>>>(gi1A, gi1B, gh1, hL1, out_h1,
                                 post_W, post_b, out_output);
}

// round 10
// speedup vs baseline: 1.4191x; 1.0564x over previous
#include <cuda_runtime.h>
#include <math.h>
#include <stdint.h>

#define NB 512
#define NH 1024
#define NS 64
#define NM 10
#define CAT_LD 1056
#define NBNH (NB * NH)
#define G3 (3 * NH)
#define NJOBS 8

// ---------------- scratch (device globals) ----------------------------------
__device__ __align__(1024) float g_Wt[NH * NH];
__device__ __align__(1024) float g_preW[NH * CAT_LD];
__device__ __align__(1024) float g_upart[8 * NBNH];
__device__ __align__(1024) float g_cat[NB * CAT_LD];
__device__ __align__(1024) float g_xpart[6 * NBNH];
__device__ __align__(1024) float g_x0[NBNH];
__device__ __align__(1024) float g_gi0[NB * G3];
__device__ __align__(1024) float g_gh0[NB * G3];
__device__ __align__(1024) float g_gh1[NB * G3];
__device__ __align__(1024) float g_gi1A[NB * G3];
__device__ __align__(1024) float g_gi1B[NB * G3];
__device__ __align__(1024) float g_gi1C[NB * G3];

struct Jobs {
    const float* A[NJOBS]; const float* B[NJOBS];
    const float* bias[NJOBS]; float* C[NJOBS];
    int lda[NJOBS], ldb[NJOBS], ldc[NJOBS], nchunk[NJOBS], nx[NJOBS], split[NJOBS];
};

// ---------------- helpers ----------------------------------------------------
__device__ __forceinline__ uint32_t smem_u32(const void* p) {
    uint32_t a;
    asm("{ .reg .u64 t; cvta.to.shared.u64 t, %1; cvt.u32.u64 %0, t; }"
        : "=r"(a) : "l"(p));
    return a;
}
__device__ __forceinline__ uint32_t tf32_rna(float x) {
    uint32_t r;
    asm("cvt.rna.tf32.f32 %0, %1;" : "=r"(r) : "f"(x));
    return r;
}
__device__ __forceinline__ void mma_tf32(float* c, uint32_t a0, uint32_t a1,
                                         uint32_t a2, uint32_t a3,
                                         uint32_t b0, uint32_t b1) {
    asm volatile(
        "mma.sync.aligned.m16n8k8.row.col.f32.tf32.tf32.f32 "
        "{%0,%1,%2,%3}, {%4,%5,%6,%7}, {%8,%9}, {%0,%1,%2,%3};"
        : "+f"(c[0]), "+f"(c[1]), "+f"(c[2]), "+f"(c[3])
        : "r"(a0), "r"(a1), "r"(a2), "r"(a3), "r"(b0), "r"(b1));
}
__device__ __forceinline__ void cp16(uint32_t dst, const void* src) {
    asm volatile("cp.async.cg.shared.global [%0], [%1], 16;"
                 :: "r"(dst), "l"(src));
}
__device__ __forceinline__ void ldsm4(uint32_t& r0, uint32_t& r1, uint32_t& r2,
                                      uint32_t& r3, uint32_t addr) {
    asm volatile("ldmatrix.sync.aligned.m8n8.x4.shared.b16 {%0,%1,%2,%3}, [%4];"
                 : "=r"(r0), "=r"(r1), "=r"(r2), "=r"(r3) : "r"(addr));
}

// ---------------- tf32 warp-MMA GEMM (job-table batched) --------------------
// 4-stage cp.async pipeline, ONE __syncthreads per chunk, exact tail waits.
#define NSTAGE 4
#define STG_B 20480
#define DYN_SMEM (NSTAGE * STG_B)   // 81920

__global__ __launch_bounds__(256, 2) void gemm_mma(Jobs jobs)
{
    const int z = blockIdx.z;
    if (blockIdx.x >= jobs.nx[z]) return;

    extern __shared__ float dyn[];
    __shared__ float bias_s[128];

    const float* A = jobs.A[z];
    const float* B = jobs.B[z];
    const float* bias = jobs.bias[z];
    float* C = jobs.C[z];
    const int lda = jobs.lda[z], ldb = jobs.ldb[z], ldc = jobs.ldc[z];
    const int nchunk = jobs.nchunk[z], split = jobs.split[z];

    const int tid = threadIdx.x;
    const int wid = tid >> 5, lane = tid & 31;
    const int g = lane >> 2, tg = lane & 3;
    const int wm = wid >> 2, wn = wid & 3;
    const int lr = lane & 7, lq = lane >> 3;
    const int n0 = blockIdx.x * 128;
    const int m0 = blockIdx.y * 128;

    if (tid < 128) bias_s[tid] = bias ? bias[n0 + tid] : 0.f;

    const uint32_t smem_base = smem_u32(dyn);
    const uint32_t a_off = (uint32_t)(((wm * 64 + (lq & 1) * 8 + lr) * 20 +
                                      (lq >> 1) * 4) * 4);
    const uint32_t b_off = (uint32_t)((2560 + (wn * 32 + (lq >> 1) * 8 + lr) * 20 +
                                      (lq & 1) * 4) * 4);
    const int lr0 = tid >> 2,          lk0 = tid & 3;
    const int lr1 = (tid + 256) >> 2,  lk1 = (tid + 256) & 3;

    auto load_chunk = [&](int c, int s) {
        const uint32_t sa = smem_base + s * STG_B;
        const uint32_t sb = sa + 10240;
        const float* Ag = A + (size_t)m0 * lda + c * 16;
        const float* Bg = B + (size_t)n0 * ldb + c * 16;
        cp16(sa + (lr0 * 20 + lk0 * 4) * 4, Ag + (size_t)lr0 * lda + lk0 * 4);
        cp16(sa + (lr1 * 20 + lk1 * 4) * 4, Ag + (size_t)lr1 * lda + lk1 * 4);
        cp16(sb + (lr0 * 20 + lk0 * 4) * 4, Bg + (size_t)lr0 * ldb + lk0 * 4);
        cp16(sb + (lr1 * 20 + lk1 * 4) * 4, Bg + (size_t)lr1 * ldb + lk1 * 4);
        asm volatile("cp.async.commit_group;" ::: "memory");
    };

    float acc[4][4][4];
#pragma unroll
    for (int mt = 0; mt < 4; mt++)
#pragma unroll
        for (int nt = 0; nt < 4; nt++)
#pragma unroll
            for (int q = 0; q < 4; q++) acc[mt][nt][q] = 0.f;

    load_chunk(0, 0); load_chunk(1, 1); load_chunk(2, 2);

    for (int t = 0; t < nchunk; t++) {
        if (t < nchunk - 2)
            asm volatile("cp.async.wait_group 2;" ::: "memory");
        else if (t == nchunk - 2)
            asm volatile("cp.async.wait_group 1;" ::: "memory");
        else
            asm volatile("cp.async.wait_group 0;" ::: "memory");
        __syncthreads();
        if (t + 3 < nchunk) load_chunk(t + 3, (t + 3) & 3);

        const uint32_t sbase = smem_base + (t & 3) * STG_B;
        const uint32_t abase = sbase + a_off;
        const uint32_t bbase = sbase + b_off;

#pragma unroll
        for (int ks = 0; ks < 2; ks++) {
            uint32_t au[4][4], bu[4][2];
#pragma unroll
            for (int mt = 0; mt < 4; mt++)
                ldsm4(au[mt][0], au[mt][1], au[mt][2], au[mt][3],
                      abase + mt * 1280 + ks * 32);
#pragma unroll
            for (int j = 0; j < 2; j++)
                ldsm4(bu[2 * j][0], bu[2 * j][1], bu[2 * j + 1][0],
                      bu[2 * j + 1][1], bbase + j * 1280 + ks * 32);

            if (!split) {
#pragma unroll
                for (int mt = 0; mt < 4; mt++)
#pragma unroll
                    for (int nt = 0; nt < 4; nt++)
                        mma_tf32(acc[mt][nt], au[mt][0], au[mt][1], au[mt][2],
                                 au[mt][3], bu[nt][0], bu[nt][1]);
            } else {
                uint32_t bh[4][2], bl[4][2];
#pragma unroll
                for (int nt = 0; nt < 4; nt++)
#pragma unroll
                    for (int q = 0; q < 2; q++) {
                        float v = __uint_as_float(bu[nt][q]);
                        uint32_t hi = tf32_rna(v);
                        bh[nt][q] = hi;
                        bl[nt][q] = tf32_rna(v - __uint_as_float(hi));
                    }
#pragma unroll
                for (int mt = 0; mt < 4; mt++) {
                    uint32_t ah[4], al[4];
#pragma unroll
                    for (int q = 0; q < 4; q++) {
                        float v = __uint_as_float(au[mt][q]);
                        ah[q] = tf32_rna(v);
                        al[q] = tf32_rna(v - __uint_as_float(ah[q]));
                    }
#pragma unroll
                    for (int nt = 0; nt < 4; nt++) {
                        mma_tf32(acc[mt][nt], al[0], al[1], al[2], al[3],
                                 bh[nt][0], bh[nt][1]);
                        mma_tf32(acc[mt][nt], ah[0], ah[1], ah[2], ah[3],
                                 bl[nt][0], bl[nt][1]);
                        mma_tf32(acc[mt][nt], ah[0], ah[1], ah[2], ah[3],
                                 bh[nt][0], bh[nt][1]);
                    }
                }
            }
        }
    }

#pragma unroll
    for (int mt = 0; mt < 4; mt++) {
        const int row = m0 + wm * 64 + mt * 16 + g;
        float* Cr0 = C + (size_t)row * ldc + n0;
        float* Cr1 = Cr0 + 8 * ldc;
#pragma unroll
        for (int nt = 0; nt < 4; nt++) {
            const int col = wn * 32 + nt * 8 + tg * 2;
            float2 v0 = make_float2(acc[mt][nt][0] + bias_s[col],
                                    acc[mt][nt][1] + bias_s[col + 1]);
            float2 v1 = make_float2(acc[mt][nt][2] + bias_s[col],
                                    acc[mt][nt][3] + bias_s[col + 1]);
            *(float2*)(Cr0 + col) = v0;
            *(float2*)(Cr1 + col) = v1;
        }
    }
}

// ---------------- prep: attn_W transpose + pre_W repack ---------------------
__global__ __launch_bounds__(256) void prep_kernel(
    const float* __restrict__ attn_W, float* __restrict__ Wt,
    const float* __restrict__ pre_W, float* __restrict__ preW)
{
    if (blockIdx.y < 32) {
        __shared__ float t[32][33];
        const int tx = threadIdx.x & 31, ty = threadIdx.x >> 5;
        int x = blockIdx.x * 32 + tx;
        int y0 = blockIdx.y * 32 + ty;
#pragma unroll
        for (int j = 0; j < 32; j += 8)
            t[ty + j][tx] = attn_W[(size_t)(y0 + j) * NH + x];
        __syncthreads();
        x = blockIdx.y * 32 + tx;
        y0 = blockIdx.x * 32 + ty;
#pragma unroll
        for (int j = 0; j < 32; j += 8)
            Wt[(size_t)(y0 + j) * NH + x] = t[tx][ty + j];
    } else {
        const int n = (blockIdx.y - 32) * 32 + blockIdx.x;
        for (int k = threadIdx.x; k < CAT_LD; k += 256)
            preW[(size_t)n * CAT_LD + k] =
                (k < NH + NM) ? pre_W[(size_t)n * (NH + NM) + k] : 0.f;
    }
}

__device__ __forceinline__ float warp_sum(float v) {
#pragma unroll
    for (int o = 16; o; o >>= 1) v += __shfl_xor_sync(0xffffffffu, v, o);
    return v;
}

// ---------------- fused attention: 8-way u-reduce + online softmax ----------
__global__ __launch_bounds__(256, 3) void attn_fused(
    const float* __restrict__ enc, const float* __restrict__ upart,
    const float* __restrict__ motion, float* __restrict__ attn_out,
    float* __restrict__ cat)
{
    const int b = blockIdx.x;
    const int tid = threadIdx.x;
    const int lane = tid & 31, w = tid >> 5;

    __shared__ float e_raw[NS];
    __shared__ float warp_m[8], warp_z[8];
    __shared__ __align__(16) float ur_s[NH];
    __shared__ __align__(16) float ctxs[8 * NH];

    {
        float4 v = make_float4(0.f, 0.f, 0.f, 0.f);
#pragma unroll
        for (int s = 0; s < 8; s++) {
            float4 p = ((const float4*)(upart + (size_t)s * NBNH +
                                        (size_t)b * NH))[tid];
            v.x += p.x; v.y += p.y; v.z += p.z; v.w += p.w;
        }
        ((float4*)ur_s)[tid] = v;
    }
    __syncthreads();

    float4 cacc[8];
#pragma unroll
    for (int i = 0; i < 8; i++) cacc[i] = make_float4(0.f, 0.f, 0.f, 0.f);
    float m = -1e30f, Z = 0.f;
    const float4* u4 = (const float4*)ur_s;

#pragma unroll
    for (int si = 0; si < 8; si++) {
        const int s = w + si * 8;
        const float4* ep = (const float4*)(enc + ((size_t)s * NB + b) * NH);
        float4 row[8];
        float d = 0.f;
#pragma unroll
        for (int i = 0; i < 8; i++) {
            row[i] = ep[i * 32 + lane];
            float4 uv = u4[i * 32 + lane];
            d = fmaf(row[i].x, uv.x, d);
            d = fmaf(row[i].y, uv.y, d);
            d = fmaf(row[i].z, uv.z, d);
            d = fmaf(row[i].w, uv.w, d);
        }
        d = warp_sum(d);
        if (lane == 0) e_raw[s] = d;
        const float mn = fmaxf(m, d);
        const float scale = __expf(m - mn);
        const float wgt = __expf(d - mn);
        Z = Z * scale + wgt;
#pragma unroll
        for (int i = 0; i < 8; i++) {
            cacc[i].x = fmaf(cacc[i].x, scale, wgt * row[i].x);
            cacc[i].y = fmaf(cacc[i].y, scale, wgt * row[i].y);
            cacc[i].z = fmaf(cacc[i].z, scale, wgt * row[i].z);
            cacc[i].w = fmaf(cacc[i].w, scale, wgt * row[i].w);
        }
        m = mn;
    }

    if (lane == 0) { warp_m[w] = m; warp_z[w] = Z; }
    float4* cs = (float4*)(ctxs + w * NH);
#pragma unroll
    for (int i = 0; i < 8; i++) cs[i * 32 + lane] = cacc[i];
    __syncthreads();

    float gm = warp_m[0];
#pragma unroll
    for (int ww = 1; ww < 8; ww++) gm = fmaxf(gm, warp_m[ww]);
    float gZ = 0.f;
#pragma unroll
    for (int ww = 0; ww < 8; ww++) gZ += warp_z[ww] * __expf(warp_m[ww] - gm);
    const float invZ = 1.f / gZ;

    if (tid < NS) attn_out[(size_t)b * NS + tid] = __expf(e_raw[tid] - gm) * invZ;
    if (tid < NM) cat[(size_t)b * CAT_LD + tid] = motion[(size_t)b * NM + tid];
    if (tid < CAT_LD - NH - NM)
        cat[(size_t)b * CAT_LD + NH + NM + tid] = 0.f;

    float4 a = make_float4(0.f, 0.f, 0.f, 0.f);
#pragma unroll
    for (int ww = 0; ww < 8; ww++) {
        const float sc = __expf(warp_m[ww] - gm);
        float4 v = *(const float4*)&ctxs[ww * NH + tid * 4];
        a.x = fmaf(v.x, sc, a.x);
        a.y = fmaf(v.y, sc, a.y);
        a.z = fmaf(v.z, sc, a.z);
        a.w = fmaf(v.w, sc, a.w);
    }
    float* cp = cat + (size_t)b * CAT_LD + NM + tid * 4;
    *(float2*)cp       = make_float2(a.x * invZ, a.y * invZ);
    *(float2*)(cp + 2) = make_float2(a.z * invZ, a.w * invZ);
}

// ---------------- x0 split-K reduce (6 partials) ----------------------------
__global__ __launch_bounds__(256) void xreduce(const float* __restrict__ p,
                                               float* __restrict__ x0)
{
    const int i = (blockIdx.x * 256 + threadIdx.x) * 4;
    float4 v = *(const float4*)(p + i);
#pragma unroll
    for (int s = 1; s < 6; s++) {
        float4 w = *(const float4*)(p + (size_t)s * NBNH + i);
        v.x += w.x; v.y += w.y; v.z += w.z; v.w += w.w;
    }
    *(float4*)(x0 + i) = v;
}

// ---------------- GRU gate pointwise (layer 0) ------------------------------
__global__ __launch_bounds__(256) void gate_kernel(
    const float* __restrict__ gi, const float* __restrict__ gh,
    const float* __restrict__ hprev, float* __restrict__ out_h)
{
    const int idx = blockIdx.x * blockDim.x + threadIdx.x;
    const int b = idx >> 10, n = idx & (NH - 1);
    const float* gib = gi + (size_t)b * G3;
    const float* ghb = gh + (size_t)b * G3;
    float ir = gib[n], iz = gib[NH + n], inn = gib[2 * NH + n];
    float hr = ghb[n], hz = ghb[NH + n], hn = ghb[2 * NH + n];
    float r = 1.f / (1.f + expf(-(ir + hr)));
    float z = 1.f / (1.f + expf(-(iz + hz)));
    float nn = tanhf(inn + r * hn);
    out_h[idx] = (1.f - z) * nn + z * hprev[idx];
}

// ---------------- fused gate(layer 1, 3-way split-K gi) + post linear -------
__global__ __launch_bounds__(256) void gatepost_kernel(
    const float* __restrict__ giA, const float* __restrict__ giB,
    const float* __restrict__ giC, const float* __restrict__ gh,
    const float* __restrict__ hprev, float* __restrict__ out_h,
    const float* __restrict__ W, const float* __restrict__ bias,
    float* __restrict__ out)
{
    const int b = blockIdx.x;
    const int tid = threadIdx.x;

    float hv[4];
#pragma unroll
    for (int q = 0; q < 4; q++) {
        const int n = tid * 4 + q;
        const size_t o = (size_t)b * G3 + n;
        float ir = giA[o] + giB[o] + giC[o];
        float iz = giA[o + NH] + giB[o + NH] + giC[o + NH];
        float inn = giA[o + 2 * NH] + giB[o + 2 * NH] + giC[o + 2 * NH];
        float hr = gh[o], hz = gh[o + NH], hn = gh[o + 2 * NH];
        float r = 1.f / (1.f + expf(-(ir + hr)));
        float z = 1.f / (1.f + expf(-(iz + hz)));
        float nn = tanhf(inn + r * hn);
        hv[q] = (1.f - z) * nn + z * hprev[(size_t)b * NH + n];
    }
    *(float4*)(out_h + (size_t)b * NH + tid * 4) =
        make_float4(hv[0], hv[1], hv[2], hv[3]);

    float acc[10];
#pragma unroll
    for (int o = 0; o < 10; o++) {
        const float4 wv = *(const float4*)(W + (size_t)o * NH + tid * 4);
        acc[o] = hv[0] * wv.x + hv[1] * wv.y + hv[2] * wv.z + hv[3] * wv.w;
    }
    __shared__ float red[10][8];
    const int lane = tid & 31, w = tid >> 5;
#pragma unroll
    for (int o = 0; o < 10; o++) {
        float v = warp_sum(acc[o]);
        if (lane == 0) red[o][w] = v;
    }
    __syncthreads();
    if (tid < 10) {
        float s = 0.f;
#pragma unroll
        for (int ww = 0; ww < 8; ww++) s += red[tid][ww];
        out[(size_t)b * 10 + tid] = s + bias[tid];
    }
}

// ---------------- host launch ------------------------------------------------
extern "C" void kernel_launch(void* const* d_in, const int* in_sizes, int n_in,
                              void* d_out, int out_size)
{
    const float* motion      = (const float*)d_in[0];
    const float* last_hidden = (const float*)d_in[1];
    const float* enc         = (const float*)d_in[2];
    const float* attn_W      = (const float*)d_in[3];
    /* d_in[4] = attn_b: unused (softmax shift-invariant) */
    const float* pre_W  = (const float*)d_in[5];
    const float* pre_b  = (const float*)d_in[6];
    const float* Wih0   = (const float*)d_in[7];
    const float* Whh0   = (const float*)d_in[8];
    const float* bih0   = (const float*)d_in[9];
    const float* bhh0   = (const float*)d_in[10];
    const float* Wih1   = (const float*)d_in[11];
    const float* Whh1   = (const float*)d_in[12];
    const float* bih1   = (const float*)d_in[13];
    const float* bhh1   = (const float*)d_in[14];
    const float* post_W = (const float*)d_in[15];
    const float* post_b = (const float*)d_in[16];

    float* out        = (float*)d_out;
    float* out_output = out;
    float* out_h0     = out + NB * 10;
    float* out_h1     = out + NB * 10 + NBNH;
    float* out_attn   = out + NB * 10 + 2 * NBNH;

    float *upart, *xpart, *cat, *x0, *gi0, *gh0, *gh1;
    float *gi1A, *gi1B, *gi1C, *preW, *Wt;
    cudaGetSymbolAddress((void**)&upart, g_upart);
    cudaGetSymbolAddress((void**)&xpart, g_xpart);
    cudaGetSymbolAddress((void**)&cat,   g_cat);
    cudaGetSymbolAddress((void**)&x0,    g_x0);
    cudaGetSymbolAddress((void**)&gi0,   g_gi0);
    cudaGetSymbolAddress((void**)&gh0,   g_gh0);
    cudaGetSymbolAddress((void**)&gh1,   g_gh1);
    cudaGetSymbolAddress((void**)&gi1A,  g_gi1A);
    cudaGetSymbolAddress((void**)&gi1B,  g_gi1B);
    cudaGetSymbolAddress((void**)&gi1C,  g_gi1C);
    cudaGetSymbolAddress((void**)&preW,  g_preW);
    cudaGetSymbolAddress((void**)&Wt,    g_Wt);

    const float* hL0 = last_hidden;
    const float* hL1 = last_hidden + NBNH;

    cudaFuncSetAttribute(gemm_mma, cudaFuncAttributeMaxDynamicSharedMemorySize,
                         DYN_SMEM);

    // 1) prep (transpose + repack)
    prep_kernel<<<dim3(32, 64), 256>>>(attn_W, Wt, pre_W, preW);

    // 2) u split-K x8 (split-tf32) -> 256 CTAs (~2/SM)
    {
        Jobs j = {};
        for (int s = 0; s < 8; s++) {
            j.A[s] = hL1 + s * 128;  j.B[s] = Wt + s * 128;
            j.bias[s] = nullptr;     j.C[s] = upart + (size_t)s * NBNH;
            j.lda[s] = NH; j.ldb[s] = NH; j.ldc[s] = NH;
            j.nchunk[s] = 8; j.nx[s] = 8; j.split[s] = 1;
        }
        gemm_mma<<<dim3(8, 4, 8), 256, DYN_SMEM>>>(j);
    }

    // 3) fused attention (8-way u reduce inside)
    attn_fused<<<NB, 256>>>(enc, upart, motion, out_attn, cat);

    // 4) pre split-K x6 -> 192 CTAs
    {
        Jobs j = {};
        for (int s = 0; s < 6; s++) {
            j.A[s] = cat + s * 176;  j.B[s] = preW + s * 176;
            j.bias[s] = (s == 0) ? pre_b : nullptr;
            j.C[s] = xpart + (size_t)s * NBNH;
            j.lda[s] = CAT_LD; j.ldb[s] = CAT_LD; j.ldc[s] = NH;
            j.nchunk[s] = 11; j.nx[s] = 8; j.split[s] = 0;
        }
        gemm_mma<<<dim3(8, 4, 6), 256, DYN_SMEM>>>(j);
    }
    xreduce<<<NBNH / 1024, 256>>>(xpart, x0);

    // 5) BIG combo: gi0 + gh0 + gh1 — 288 CTAs (~2/SM)
    {
        Jobs j = {};
        j.A[0] = x0;  j.B[0] = Wih0; j.bias[0] = bih0; j.C[0] = gi0;
        j.A[1] = hL0; j.B[1] = Whh0; j.bias[1] = bhh0; j.C[1] = gh0;
        j.A[2] = hL1; j.B[2] = Whh1; j.bias[2] = bhh1; j.C[2] = gh1;
        for (int s = 0; s < 3; s++) {
            j.lda[s] = NH; j.ldb[s] = NH; j.ldc[s] = G3;
            j.nchunk[s] = 64; j.nx[s] = 24; j.split[s] = 0;
        }
        gemm_mma<<<dim3(24, 4, 3), 256, DYN_SMEM>>>(j);
    }
    gate_kernel<<<NBNH / 256, 256>>>(gi0, gh0, hL0, out_h0);

    // 6) gi1 split-K x3 (chunks 22/22/20) -> 288 CTAs
    {
        Jobs j = {};
        const int koff[3] = {0, 352, 704};
        const int nch[3] = {22, 22, 20};
        float* dst[3] = {gi1A, gi1B, gi1C};
        for (int k = 0; k < 3; k++) {
            j.A[k] = out_h0 + koff[k]; j.B[k] = Wih1 + koff[k];
            j.bias[k] = k ? nullptr : bih1;
            j.C[k] = dst[k];
            j.lda[k] = NH; j.ldb[k] = NH; j.ldc[k] = G3;
            j.nchunk[k] = nch[k]; j.nx[k] = 24; j.split[k] = 0;
        }
        gemm_mma<<<dim3(24, 4, 3), 256, DYN_SMEM>>>(j);
    }
    gatepost_kernel<<<NB, 256>>>(gi1A, gi1B, gi1C, gh1, hL1, out_h1,
                                 post_W, post_b, out_output);
}

// round 11
// speedup vs baseline: 1.6265x; 1.1462x over previous
#include <cuda_runtime.h>
#include <cuda_fp16.h>
#include <math.h>
#include <stdint.h>

#define NB 512
#define NH 1024
#define NS 64
#define NM 10
#define CAT_LD 1056
#define NBNH (NB * NH)
#define G3 (3 * NH)
#define NJOBS 8

// ---------------- scratch (device globals) ----------------------------------
__device__ __align__(1024) float  g_Wt[NH * NH];          // attn_W^T (fp32, tf32 path)
__device__ __align__(1024) __half g_preWh[NH * CAT_LD];
__device__ __align__(1024) __half g_Wih0h[G3 * NH];
__device__ __align__(1024) __half g_Whh0h[G3 * NH];
__device__ __align__(1024) __half g_Wih1h[G3 * NH];
__device__ __align__(1024) __half g_Whh1h[G3 * NH];
__device__ __align__(1024) __half g_hLh[2 * NBNH];        // fp16 last_hidden
__device__ __align__(1024) float  g_upart[8 * NBNH];
__device__ __align__(1024) __half g_cath[NB * CAT_LD];
__device__ __align__(1024) float  g_xpart[6 * NBNH];
__device__ __align__(1024) __half g_x0h[NBNH];
__device__ __align__(1024) __half g_h0h[NBNH];
__device__ __align__(1024) float  g_gi0[NB * G3];
__device__ __align__(1024) float  g_gh0[NB * G3];
__device__ __align__(1024) float  g_gh1[NB * G3];
__device__ __align__(1024) float  g_gi1A[NB * G3];
__device__ __align__(1024) float  g_gi1B[NB * G3];
__device__ __align__(1024) float  g_gi1C[NB * G3];

struct Jobs {
    const float* A[NJOBS]; const float* B[NJOBS];
    const float* bias[NJOBS]; float* C[NJOBS];
    int lda[NJOBS], ldb[NJOBS], ldc[NJOBS], nchunk[NJOBS], nx[NJOBS], split[NJOBS];
};
struct JobsH {
    const __half* A[NJOBS]; const __half* B[NJOBS];
    const float* bias[NJOBS]; float* C[NJOBS];
    int lda[NJOBS], ldb[NJOBS], ldc[NJOBS], nchunk[NJOBS], nx[NJOBS];
};

// ---------------- helpers ----------------------------------------------------
__device__ __forceinline__ uint32_t smem_u32(const void* p) {
    uint32_t a;
    asm("{ .reg .u64 t; cvta.to.shared.u64 t, %1; cvt.u32.u64 %0, t; }"
        : "=r"(a) : "l"(p));
    return a;
}
__device__ __forceinline__ uint32_t tf32_rna(float x) {
    uint32_t r;
    asm("cvt.rna.tf32.f32 %0, %1;" : "=r"(r) : "f"(x));
    return r;
}
__device__ __forceinline__ void mma_tf32(float* c, uint32_t a0, uint32_t a1,
                                         uint32_t a2, uint32_t a3,
                                         uint32_t b0, uint32_t b1) {
    asm volatile(
        "mma.sync.aligned.m16n8k8.row.col.f32.tf32.tf32.f32 "
        "{%0,%1,%2,%3}, {%4,%5,%6,%7}, {%8,%9}, {%0,%1,%2,%3};"
        : "+f"(c[0]), "+f"(c[1]), "+f"(c[2]), "+f"(c[3])
        : "r"(a0), "r"(a1), "r"(a2), "r"(a3), "r"(b0), "r"(b1));
}
__device__ __forceinline__ void mma_f16(float* c, uint32_t a0, uint32_t a1,
                                        uint32_t a2, uint32_t a3,
                                        uint32_t b0, uint32_t b1) {
    asm volatile(
        "mma.sync.aligned.m16n8k16.row.col.f32.f16.f16.f32 "
        "{%0,%1,%2,%3}, {%4,%5,%6,%7}, {%8,%9}, {%0,%1,%2,%3};"
        : "+f"(c[0]), "+f"(c[1]), "+f"(c[2]), "+f"(c[3])
        : "r"(a0), "r"(a1), "r"(a2), "r"(a3), "r"(b0), "r"(b1));
}
__device__ __forceinline__ void cp16(uint32_t dst, const void* src) {
    asm volatile("cp.async.cg.shared.global [%0], [%1], 16;"
                 :: "r"(dst), "l"(src));
}
__device__ __forceinline__ void ldsm4(uint32_t& r0, uint32_t& r1, uint32_t& r2,
                                      uint32_t& r3, uint32_t addr) {
    asm volatile("ldmatrix.sync.aligned.m8n8.x4.shared.b16 {%0,%1,%2,%3}, [%4];"
                 : "=r"(r0), "=r"(r1), "=r"(r2), "=r"(r3) : "r"(addr));
}

#define NSTAGE 4
#define STG_B 20480
#define DYN_SMEM (NSTAGE * STG_B)   // 81920

// ---------------- tf32 GEMM (split path only: u) -----------------------------
__global__ __launch_bounds__(256, 2) void gemm_mma(Jobs jobs)
{
    const int z = blockIdx.z;
    if (blockIdx.x >= jobs.nx[z]) return;

    extern __shared__ float dyn[];
    __shared__ float bias_s[128];

    const float* A = jobs.A[z];
    const float* B = jobs.B[z];
    const float* bias = jobs.bias[z];
    float* C = jobs.C[z];
    const int lda = jobs.lda[z], ldb = jobs.ldb[z], ldc = jobs.ldc[z];
    const int nchunk = jobs.nchunk[z], split = jobs.split[z];

    const int tid = threadIdx.x;
    const int wid = tid >> 5, lane = tid & 31;
    const int g = lane >> 2, tg = lane & 3;
    const int wm = wid >> 2, wn = wid & 3;
    const int lq = lane >> 3, lr = lane & 7;
    const int n0 = blockIdx.x * 128;
    const int m0 = blockIdx.y * 128;

    if (tid < 128) bias_s[tid] = bias ? bias[n0 + tid] : 0.f;

    const uint32_t smem_base = smem_u32(dyn);
    const uint32_t a_off = (uint32_t)(((wm * 64 + (lq & 1) * 8 + lr) * 20 +
                                      (lq >> 1) * 4) * 4);
    const uint32_t b_off = (uint32_t)((2560 + (wn * 32 + (lq >> 1) * 8 + lr) * 20 +
                                      (lq & 1) * 4) * 4);
    const int lr0 = tid >> 2,          lk0 = tid & 3;
    const int lr1 = (tid + 256) >> 2,  lk1 = (tid + 256) & 3;

    auto load_chunk = [&](int c, int s) {
        const uint32_t sa = smem_base + s * STG_B;
        const uint32_t sb = sa + 10240;
        const float* Ag = A + (size_t)m0 * lda + c * 16;
        const float* Bg = B + (size_t)n0 * ldb + c * 16;
        cp16(sa + (lr0 * 20 + lk0 * 4) * 4, Ag + (size_t)lr0 * lda + lk0 * 4);
        cp16(sa + (lr1 * 20 + lk1 * 4) * 4, Ag + (size_t)lr1 * lda + lk1 * 4);
        cp16(sb + (lr0 * 20 + lk0 * 4) * 4, Bg + (size_t)lr0 * ldb + lk0 * 4);
        cp16(sb + (lr1 * 20 + lk1 * 4) * 4, Bg + (size_t)lr1 * ldb + lk1 * 4);
        asm volatile("cp.async.commit_group;" ::: "memory");
    };

    float acc[4][4][4];
#pragma unroll
    for (int mt = 0; mt < 4; mt++)
#pragma unroll
        for (int nt = 0; nt < 4; nt++)
#pragma unroll
            for (int q = 0; q < 4; q++) acc[mt][nt][q] = 0.f;

    load_chunk(0, 0); load_chunk(1, 1); load_chunk(2, 2);

    for (int t = 0; t < nchunk; t++) {
        if (t < nchunk - 2)
            asm volatile("cp.async.wait_group 2;" ::: "memory");
        else if (t == nchunk - 2)
            asm volatile("cp.async.wait_group 1;" ::: "memory");
        else
            asm volatile("cp.async.wait_group 0;" ::: "memory");
        __syncthreads();
        if (t + 3 < nchunk) load_chunk(t + 3, (t + 3) & 3);

        const uint32_t sbase = smem_base + (t & 3) * STG_B;
        const uint32_t abase = sbase + a_off;
        const uint32_t bbase = sbase + b_off;

#pragma unroll
        for (int ks = 0; ks < 2; ks++) {
            uint32_t au[4][4], bu[4][2];
#pragma unroll
            for (int mt = 0; mt < 4; mt++)
                ldsm4(au[mt][0], au[mt][1], au[mt][2], au[mt][3],
                      abase + mt * 1280 + ks * 32);
#pragma unroll
            for (int j = 0; j < 2; j++)
                ldsm4(bu[2 * j][0], bu[2 * j][1], bu[2 * j + 1][0],
                      bu[2 * j + 1][1], bbase + j * 1280 + ks * 32);

            if (!split) {
#pragma unroll
                for (int mt = 0; mt < 4; mt++)
#pragma unroll
                    for (int nt = 0; nt < 4; nt++)
                        mma_tf32(acc[mt][nt], au[mt][0], au[mt][1], au[mt][2],
                                 au[mt][3], bu[nt][0], bu[nt][1]);
            } else {
                uint32_t bh[4][2], bl[4][2];
#pragma unroll
                for (int nt = 0; nt < 4; nt++)
#pragma unroll
                    for (int q = 0; q < 2; q++) {
                        float v = __uint_as_float(bu[nt][q]);
                        uint32_t hi = tf32_rna(v);
                        bh[nt][q] = hi;
                        bl[nt][q] = tf32_rna(v - __uint_as_float(hi));
                    }
#pragma unroll
                for (int mt = 0; mt < 4; mt++) {
                    uint32_t ah[4], al[4];
#pragma unroll
                    for (int q = 0; q < 4; q++) {
                        float v = __uint_as_float(au[mt][q]);
                        ah[q] = tf32_rna(v);
                        al[q] = tf32_rna(v - __uint_as_float(ah[q]));
                    }
#pragma unroll
                    for (int nt = 0; nt < 4; nt++) {
                        mma_tf32(acc[mt][nt], al[0], al[1], al[2], al[3],
                                 bh[nt][0], bh[nt][1]);
                        mma_tf32(acc[mt][nt], ah[0], ah[1], ah[2], ah[3],
                                 bl[nt][0], bl[nt][1]);
                        mma_tf32(acc[mt][nt], ah[0], ah[1], ah[2], ah[3],
                                 bh[nt][0], bh[nt][1]);
                    }
                }
            }
        }
    }

#pragma unroll
    for (int mt = 0; mt < 4; mt++) {
        const int row = m0 + wm * 64 + mt * 16 + g;
        float* Cr0 = C + (size_t)row * ldc + n0;
        float* Cr1 = Cr0 + 8 * ldc;
#pragma unroll
        for (int nt = 0; nt < 4; nt++) {
            const int col = wn * 32 + nt * 8 + tg * 2;
            float2 v0 = make_float2(acc[mt][nt][0] + bias_s[col],
                                    acc[mt][nt][1] + bias_s[col + 1]);
            float2 v1 = make_float2(acc[mt][nt][2] + bias_s[col],
                                    acc[mt][nt][3] + bias_s[col + 1]);
            *(float2*)(Cr0 + col) = v0;
            *(float2*)(Cr1 + col) = v1;
        }
    }
}

// ---------------- fp16 GEMM: C[M,N] = A[M,K]h * B[N,K]h^T + bias ------------
// K chunk = 32 halves; rows stride 40 halves (80B) — conflict-free ldmatrix.
__global__ __launch_bounds__(256, 2) void gemm_h16(JobsH jobs)
{
    const int z = blockIdx.z;
    if (blockIdx.x >= jobs.nx[z]) return;

    extern __shared__ float dyn[];
    __shared__ float bias_s[128];

    const __half* A = jobs.A[z];
    const __half* B = jobs.B[z];
    const float* bias = jobs.bias[z];
    float* C = jobs.C[z];
    const int lda = jobs.lda[z], ldb = jobs.ldb[z], ldc = jobs.ldc[z];
    const int nchunk = jobs.nchunk[z];

    const int tid = threadIdx.x;
    const int wid = tid >> 5, lane = tid & 31;
    const int g = lane >> 2, tg = lane & 3;
    const int wm = wid >> 2, wn = wid & 3;
    const int n0 = blockIdx.x * 128;
    const int m0 = blockIdx.y * 128;

    if (tid < 128) bias_s[tid] = bias ? bias[n0 + tid] : 0.f;

    const uint32_t smem_base = smem_u32(dyn);
    // ldmatrix lane byte offsets within a stage
    const uint32_t a_off = (uint32_t)(((wm * 64 + (lane & 15)) * 40 +
                                       (lane >> 4) * 8) * 2);
    const uint32_t b_off = (uint32_t)(10240 +
        ((wn * 32 + (lane & 7) + ((lane >> 4) << 3)) * 40 +
         ((lane >> 3) & 1) * 8) * 2);

    const int lr0 = tid >> 1;           // 0..127 row
    const int sg0 = (tid & 1) * 2;      // segments sg0, sg0+1 (of 4 per row)

    auto load_chunk = [&](int c, int s) {
        const uint32_t sa = smem_base + s * STG_B;
        const uint32_t sb = sa + 10240;
        const __half* Ag = A + (size_t)m0 * lda + c * 32;
        const __half* Bg = B + (size_t)n0 * ldb + c * 32;
#pragma unroll
        for (int q = 0; q < 2; q++) {
            const int sg = sg0 + q;
            cp16(sa + (lr0 * 40 + sg * 8) * 2, Ag + (size_t)lr0 * lda + sg * 8);
            cp16(sb + (lr0 * 40 + sg * 8) * 2, Bg + (size_t)lr0 * ldb + sg * 8);
        }
        asm volatile("cp.async.commit_group;" ::: "memory");
    };

    float acc[4][4][4];
#pragma unroll
    for (int mt = 0; mt < 4; mt++)
#pragma unroll
        for (int nt = 0; nt < 4; nt++)
#pragma unroll
            for (int q = 0; q < 4; q++) acc[mt][nt][q] = 0.f;

    load_chunk(0, 0);
    if (nchunk > 1) load_chunk(1, 1);
    if (nchunk > 2) load_chunk(2, 2);

    for (int t = 0; t < nchunk; t++) {
        if (t < nchunk - 2)
            asm volatile("cp.async.wait_group 2;" ::: "memory");
        else if (t == nchunk - 2)
            asm volatile("cp.async.wait_group 1;" ::: "memory");
        else
            asm volatile("cp.async.wait_group 0;" ::: "memory");
        __syncthreads();
        if (t + 3 < nchunk) load_chunk(t + 3, (t + 3) & 3);

        const uint32_t sbase = smem_base + (t & 3) * STG_B;
        const uint32_t abase = sbase + a_off;
        const uint32_t bbase = sbase + b_off;

#pragma unroll
        for (int ks = 0; ks < 2; ks++) {
            uint32_t au[4][4], bu[4][2];
#pragma unroll
            for (int mt = 0; mt < 4; mt++)
                ldsm4(au[mt][0], au[mt][1], au[mt][2], au[mt][3],
                      abase + mt * 1280 + ks * 32);
#pragma unroll
            for (int j = 0; j < 2; j++)
                ldsm4(bu[2 * j][0], bu[2 * j][1], bu[2 * j + 1][0],
                      bu[2 * j + 1][1], bbase + j * 1280 + ks * 32);
#pragma unroll
            for (int mt = 0; mt < 4; mt++)
#pragma unroll
                for (int nt = 0; nt < 4; nt++)
                    mma_f16(acc[mt][nt], au[mt][0], au[mt][1], au[mt][2],
                            au[mt][3], bu[nt][0], bu[nt][1]);
        }
    }

#pragma unroll
    for (int mt = 0; mt < 4; mt++) {
        const int row = m0 + wm * 64 + mt * 16 + g;
        float* Cr0 = C + (size_t)row * ldc + n0;
        float* Cr1 = Cr0 + 8 * ldc;
#pragma unroll
        for (int nt = 0; nt < 4; nt++) {
            const int col = wn * 32 + nt * 8 + tg * 2;
            float2 v0 = make_float2(acc[mt][nt][0] + bias_s[col],
                                    acc[mt][nt][1] + bias_s[col + 1]);
            float2 v1 = make_float2(acc[mt][nt][2] + bias_s[col],
                                    acc[mt][nt][3] + bias_s[col + 1]);
            *(float2*)(Cr0 + col) = v0;
            *(float2*)(Cr1 + col) = v1;
        }
    }
}

// ---------------- prep: transpose + repack + fp16 weight/hidden converts ----
#define CONV_F4_TOTAL 3407872         // 4*786432 + 262144
#define W4 786432                     // G3*NH/4

__global__ __launch_bounds__(256) void prep_kernel(
    const float* __restrict__ attn_W, float* __restrict__ Wt,
    const float* __restrict__ pre_W, __half* __restrict__ preWh,
    const float* __restrict__ Wih0, const float* __restrict__ Whh0,
    const float* __restrict__ Wih1, const float* __restrict__ Whh1,
    const float* __restrict__ last_hidden)
{
    const int y = blockIdx.y;
    if (y < 32) {
        __shared__ float t[32][33];
        const int tx = threadIdx.x & 31, ty = threadIdx.x >> 5;
        int x = blockIdx.x * 32 + tx;
        int y0 = y * 32 + ty;
#pragma unroll
        for (int j = 0; j < 32; j += 8)
            t[ty + j][tx] = attn_W[(size_t)(y0 + j) * NH + x];
        __syncthreads();
        x = y * 32 + tx;
        y0 = blockIdx.x * 32 + ty;
#pragma unroll
        for (int j = 0; j < 32; j += 8)
            Wt[(size_t)(y0 + j) * NH + x] = t[tx][ty + j];
    } else if (y < 64) {
        const int n = (y - 32) * 32 + blockIdx.x;
        for (int k = threadIdx.x; k < CAT_LD; k += 256)
            preWh[(size_t)n * CAT_LD + k] =
                (k < NH + NM) ? __float2half(pre_W[(size_t)n * (NH + NM) + k])
                              : __half(0.f);
    } else {
        // fp16 conversion: 3,407,872 float4s over 1664 CTAs x 2048 each
        const int cta = (y - 64) * 32 + blockIdx.x;
        const int base = cta * 2048 + threadIdx.x;
#pragma unroll
        for (int it = 0; it < 8; it++) {
            const int e = base + it * 256;
            const float* src; __half* dst; int le;
            if (e < W4)            { src = Wih0; dst = g_Wih0h; le = e; }
            else if (e < 2 * W4)   { src = Whh0; dst = g_Whh0h; le = e - W4; }
            else if (e < 3 * W4)   { src = Wih1; dst = g_Wih1h; le = e - 2 * W4; }
            else if (e < 4 * W4)   { src = Whh1; dst = g_Whh1h; le = e - 3 * W4; }
            else                   { src = last_hidden; dst = g_hLh; le = e - 4 * W4; }
            float4 v = ((const float4*)src)[le];
            __half2* d2 = (__half2*)dst + (size_t)le * 2;
            d2[0] = __floats2half2_rn(v.x, v.y);
            d2[1] = __floats2half2_rn(v.z, v.w);
        }
    }
}

__device__ __forceinline__ float warp_sum(float v) {
#pragma unroll
    for (int o = 16; o; o >>= 1) v += __shfl_xor_sync(0xffffffffu, v, o);
    return v;
}

// ---------------- fused attention: 8-way u-reduce + online softmax ----------
__global__ __launch_bounds__(256, 3) void attn_fused(
    const float* __restrict__ enc, const float* __restrict__ upart,
    const float* __restrict__ motion, float* __restrict__ attn_out,
    __half* __restrict__ cath)
{
    const int b = blockIdx.x;
    const int tid = threadIdx.x;
    const int lane = tid & 31, w = tid >> 5;

    __shared__ float e_raw[NS];
    __shared__ float warp_m[8], warp_z[8];
    __shared__ __align__(16) float ur_s[NH];
    __shared__ __align__(16) float ctxs[8 * NH];

    {
        float4 v = make_float4(0.f, 0.f, 0.f, 0.f);
#pragma unroll
        for (int s = 0; s < 8; s++) {
            float4 p = ((const float4*)(upart + (size_t)s * NBNH +
                                        (size_t)b * NH))[tid];
            v.x += p.x; v.y += p.y; v.z += p.z; v.w += p.w;
        }
        ((float4*)ur_s)[tid] = v;
    }
    __syncthreads();

    float4 cacc[8];
#pragma unroll
    for (int i = 0; i < 8; i++) cacc[i] = make_float4(0.f, 0.f, 0.f, 0.f);
    float m = -1e30f, Z = 0.f;
    const float4* u4 = (const float4*)ur_s;

#pragma unroll
    for (int si = 0; si < 8; si++) {
        const int s = w + si * 8;
        const float4* ep = (const float4*)(enc + ((size_t)s * NB + b) * NH);
        float4 row[8];
        float d = 0.f;
#pragma unroll
        for (int i = 0; i < 8; i++) {
            row[i] = ep[i * 32 + lane];
            float4 uv = u4[i * 32 + lane];
            d = fmaf(row[i].x, uv.x, d);
            d = fmaf(row[i].y, uv.y, d);
            d = fmaf(row[i].z, uv.z, d);
            d = fmaf(row[i].w, uv.w, d);
        }
        d = warp_sum(d);
        if (lane == 0) e_raw[s] = d;
        const float mn = fmaxf(m, d);
        const float scale = __expf(m - mn);
        const float wgt = __expf(d - mn);
        Z = Z * scale + wgt;
#pragma unroll
        for (int i = 0; i < 8; i++) {
            cacc[i].x = fmaf(cacc[i].x, scale, wgt * row[i].x);
            cacc[i].y = fmaf(cacc[i].y, scale, wgt * row[i].y);
            cacc[i].z = fmaf(cacc[i].z, scale, wgt * row[i].z);
            cacc[i].w = fmaf(cacc[i].w, scale, wgt * row[i].w);
        }
        m = mn;
    }

    if (lane == 0) { warp_m[w] = m; warp_z[w] = Z; }
    float4* cs = (float4*)(ctxs + w * NH);
#pragma unroll
    for (int i = 0; i < 8; i++) cs[i * 32 + lane] = cacc[i];
    __syncthreads();

    float gm = warp_m[0];
#pragma unroll
    for (int ww = 1; ww < 8; ww++) gm = fmaxf(gm, warp_m[ww]);
    float gZ = 0.f;
#pragma unroll
    for (int ww = 0; ww < 8; ww++) gZ += warp_z[ww] * __expf(warp_m[ww] - gm);
    const float invZ = 1.f / gZ;

    if (tid < NS) attn_out[(size_t)b * NS + tid] = __expf(e_raw[tid] - gm) * invZ;
    if (tid < NM)
        cath[(size_t)b * CAT_LD + tid] = __float2half(motion[(size_t)b * NM + tid]);
    if (tid < CAT_LD - NH - NM)
        cath[(size_t)b * CAT_LD + NH + NM + tid] = __half(0.f);

    float4 a = make_float4(0.f, 0.f, 0.f, 0.f);
#pragma unroll
    for (int ww = 0; ww < 8; ww++) {
        const float sc = __expf(warp_m[ww] - gm);
        float4 v = *(const float4*)&ctxs[ww * NH + tid * 4];
        a.x = fmaf(v.x, sc, a.x);
        a.y = fmaf(v.y, sc, a.y);
        a.z = fmaf(v.z, sc, a.z);
        a.w = fmaf(v.w, sc, a.w);
    }
    __half* cp = cath + (size_t)b * CAT_LD + NM + tid * 4;
    *(__half2*)cp       = __floats2half2_rn(a.x * invZ, a.y * invZ);
    *(__half2*)(cp + 2) = __floats2half2_rn(a.z * invZ, a.w * invZ);
}

// ---------------- x0 split-K reduce (6 partials) -> fp16 --------------------
__global__ __launch_bounds__(256) void xreduce(const float* __restrict__ p,
                                               __half* __restrict__ x0h)
{
    const int i = (blockIdx.x * 256 + threadIdx.x) * 4;
    float4 v = *(const float4*)(p + i);
#pragma unroll
    for (int s = 1; s < 6; s++) {
        float4 w = *(const float4*)(p + (size_t)s * NBNH + i);
        v.x += w.x; v.y += w.y; v.z += w.z; v.w += w.w;
    }
    *(__half2*)(x0h + i)     = __floats2half2_rn(v.x, v.y);
    *(__half2*)(x0h + i + 2) = __floats2half2_rn(v.z, v.w);
}

// ---------------- GRU gate pointwise (layer 0) + fp16 copy ------------------
__global__ __launch_bounds__(256) void gate_kernel(
    const float* __restrict__ gi, const float* __restrict__ gh,
    const float* __restrict__ hprev, float* __restrict__ out_h,
    __half* __restrict__ out_h16)
{
    const int idx = blockIdx.x * blockDim.x + threadIdx.x;
    const int b = idx >> 10, n = idx & (NH - 1);
    const float* gib = gi + (size_t)b * G3;
    const float* ghb = gh + (size_t)b * G3;
    float ir = gib[n], iz = gib[NH + n], inn = gib[2 * NH + n];
    float hr = ghb[n], hz = ghb[NH + n], hn = ghb[2 * NH + n];
    float r = 1.f / (1.f + expf(-(ir + hr)));
    float z = 1.f / (1.f + expf(-(iz + hz)));
    float nn = tanhf(inn + r * hn);
    float h = (1.f - z) * nn + z * hprev[idx];
    out_h[idx] = h;
    out_h16[idx] = __float2half(h);
}

// ---------------- fused gate(layer 1, 3-way split-K gi) + post linear -------
__global__ __launch_bounds__(256) void gatepost_kernel(
    const float* __restrict__ giA, const float* __restrict__ giB,
    const float* __restrict__ giC, const float* __restrict__ gh,
    const float* __restrict__ hprev, float* __restrict__ out_h,
    const float* __restrict__ W, const float* __restrict__ bias,
    float* __restrict__ out)
{
    const int b = blockIdx.x;
    const int tid = threadIdx.x;

    float hv[4];
#pragma unroll
    for (int q = 0; q < 4; q++) {
        const int n = tid * 4 + q;
        const size_t o = (size_t)b * G3 + n;
        float ir = giA[o] + giB[o] + giC[o];
        float iz = giA[o + NH] + giB[o + NH] + giC[o + NH];
        float inn = giA[o + 2 * NH] + giB[o + 2 * NH] + giC[o + 2 * NH];
        float hr = gh[o], hz = gh[o + NH], hn = gh[o + 2 * NH];
        float r = 1.f / (1.f + expf(-(ir + hr)));
        float z = 1.f / (1.f + expf(-(iz + hz)));
        float nn = tanhf(inn + r * hn);
        hv[q] = (1.f - z) * nn + z * hprev[(size_t)b * NH + n];
    }
    *(float4*)(out_h + (size_t)b * NH + tid * 4) =
        make_float4(hv[0], hv[1], hv[2], hv[3]);

    float acc[10];
#pragma unroll
    for (int o = 0; o < 10; o++) {
        const float4 wv = *(const float4*)(W + (size_t)o * NH + tid * 4);
        acc[o] = hv[0] * wv.x + hv[1] * wv.y + hv[2] * wv.z + hv[3] * wv.w;
    }
    __shared__ float red[10][8];
    const int lane = tid & 31, w = tid >> 5;
#pragma unroll
    for (int o = 0; o < 10; o++) {
        float v = warp_sum(acc[o]);
        if (lane == 0) red[o][w] = v;
    }
    __syncthreads();
    if (tid < 10) {
        float s = 0.f;
#pragma unroll
        for (int ww = 0; ww < 8; ww++) s += red[tid][ww];
        out[(size_t)b * 10 + tid] = s + bias[tid];
    }
}

// ---------------- host launch ------------------------------------------------
extern "C" void kernel_launch(void* const* d_in, const int* in_sizes, int n_in,
                              void* d_out, int out_size)
{
    const float* motion      = (const float*)d_in[0];
    const float* last_hidden = (const float*)d_in[1];
    const float* enc         = (const float*)d_in[2];
    const float* attn_W      = (const float*)d_in[3];
    /* d_in[4] = attn_b: unused (softmax shift-invariant) */
    const float* pre_W  = (const float*)d_in[5];
    const float* pre_b  = (const float*)d_in[6];
    const float* Wih0   = (const float*)d_in[7];
    const float* Whh0   = (const float*)d_in[8];
    const float* bih0   = (const float*)d_in[9];
    const float* bhh0   = (const float*)d_in[10];
    const float* Wih1   = (const float*)d_in[11];
    const float* Whh1   = (const float*)d_in[12];
    const float* bih1   = (const float*)d_in[13];
    const float* bhh1   = (const float*)d_in[14];
    const float* post_W = (const float*)d_in[15];
    const float* post_b = (const float*)d_in[16];

    float* out        = (float*)d_out;
    float* out_output = out;
    float* out_h0     = out + NB * 10;
    float* out_h1     = out + NB * 10 + NBNH;
    float* out_attn   = out + NB * 10 + 2 * NBNH;

    float *upart, *xpart, *gi0, *gh0, *gh1, *gi1A, *gi1B, *gi1C, *Wt;
    __half *preWh, *Wih0h, *Whh0h, *Wih1h, *Whh1h, *hLh, *cath, *x0h, *h0h;
    cudaGetSymbolAddress((void**)&upart, g_upart);
    cudaGetSymbolAddress((void**)&xpart, g_xpart);
    cudaGetSymbolAddress((void**)&gi0,   g_gi0);
    cudaGetSymbolAddress((void**)&gh0,   g_gh0);
    cudaGetSymbolAddress((void**)&gh1,   g_gh1);
    cudaGetSymbolAddress((void**)&gi1A,  g_gi1A);
    cudaGetSymbolAddress((void**)&gi1B,  g_gi1B);
    cudaGetSymbolAddress((void**)&gi1C,  g_gi1C);
    cudaGetSymbolAddress((void**)&Wt,    g_Wt);
    cudaGetSymbolAddress((void**)&preWh, g_preWh);
    cudaGetSymbolAddress((void**)&Wih0h, g_Wih0h);
    cudaGetSymbolAddress((void**)&Whh0h, g_Whh0h);
    cudaGetSymbolAddress((void**)&Wih1h, g_Wih1h);
    cudaGetSymbolAddress((void**)&Whh1h, g_Whh1h);
    cudaGetSymbolAddress((void**)&hLh,   g_hLh);
    cudaGetSymbolAddress((void**)&cath,  g_cath);
    cudaGetSymbolAddress((void**)&x0h,   g_x0h);
    cudaGetSymbolAddress((void**)&h0h,   g_h0h);

    const float* hL1 = last_hidden + NBNH;
    const __half* hL0h = hLh;
    const __half* hL1h = hLh + NBNH;

    cudaFuncSetAttribute(gemm_mma, cudaFuncAttributeMaxDynamicSharedMemorySize,
                         DYN_SMEM);
    cudaFuncSetAttribute(gemm_h16, cudaFuncAttributeMaxDynamicSharedMemorySize,
                         DYN_SMEM);

    // 1) prep: transpose + repack + fp16 converts
    prep_kernel<<<dim3(32, 116), 256>>>(attn_W, Wt, pre_W, preWh,
                                        Wih0, Whh0, Wih1, Whh1, last_hidden);

    // 2) u split-K x8 (split-tf32, fp32 inputs) -> 256 CTAs
    {
        Jobs j = {};
        for (int s = 0; s < 8; s++) {
            j.A[s] = hL1 + s * 128;  j.B[s] = Wt + s * 128;
            j.bias[s] = nullptr;     j.C[s] = upart + (size_t)s * NBNH;
            j.lda[s] = NH; j.ldb[s] = NH; j.ldc[s] = NH;
            j.nchunk[s] = 8; j.nx[s] = 8; j.split[s] = 1;
        }
        gemm_mma<<<dim3(8, 4, 8), 256, DYN_SMEM>>>(j);
    }

    // 3) fused attention (8-way u reduce inside); cat written fp16
    attn_fused<<<NB, 256>>>(enc, upart, motion, out_attn, cath);

    // 4) pre split-K x6 (fp16, K chunks of 32; chunks {6,6,6,5,5,5})
    {
        JobsH j = {};
        const int koff[6] = {0, 192, 384, 576, 736, 896};
        const int nch[6]  = {6, 6, 6, 5, 5, 5};
        for (int s = 0; s < 6; s++) {
            j.A[s] = cath + koff[s]; j.B[s] = preWh + koff[s];
            j.bias[s] = (s == 0) ? pre_b : nullptr;
            j.C[s] = xpart + (size_t)s * NBNH;
            j.lda[s] = CAT_LD; j.ldb[s] = CAT_LD; j.ldc[s] = NH;
            j.nchunk[s] = nch[s]; j.nx[s] = 8;
        }
        gemm_h16<<<dim3(8, 4, 6), 256, DYN_SMEM>>>(j);
    }
    xreduce<<<NBNH / 1024, 256>>>(xpart, x0h);

    // 5) BIG combo: gi0 + gh0 + gh1 (fp16, 32 chunks each) — 288 CTAs
    {
        JobsH j = {};
        j.A[0] = x0h;  j.B[0] = Wih0h; j.bias[0] = bih0; j.C[0] = gi0;
        j.A[1] = hL0h; j.B[1] = Whh0h; j.bias[1] = bhh0; j.C[1] = gh0;
        j.A[2] = hL1h; j.B[2] = Whh1h; j.bias[2] = bhh1; j.C[2] = gh1;
        for (int s = 0; s < 3; s++) {
            j.lda[s] = NH; j.ldb[s] = NH; j.ldc[s] = G3;
            j.nchunk[s] = 32; j.nx[s] = 24;
        }
        gemm_h16<<<dim3(24, 4, 3), 256, DYN_SMEM>>>(j);
    }
    gate_kernel<<<NBNH / 256, 256>>>(gi0, gh0, last_hidden, out_h0, h0h);

    // 6) gi1 split-K x3 (fp16; chunks {11,11,10}) — 288 CTAs
    {
        JobsH j = {};
        const int koff[3] = {0, 352, 704};
        const int nch[3] = {11, 11, 10};
        float* dst[3] = {gi1A, gi1B, gi1C};
        for (int k = 0; k < 3; k++) {
            j.A[k] = h0h + koff[k]; j.B[k] = Wih1h + koff[k];
            j.bias[k] = k ? nullptr : bih1;
            j.C[k] = dst[k];
            j.lda[k] = NH; j.ldb[k] = NH; j.ldc[k] = G3;
            j.nchunk[k] = nch[k]; j.nx[k] = 24;
        }
        gemm_h16<<<dim3(24, 4, 3), 256, DYN_SMEM>>>(j);
    }
    gatepost_kernel<<<NB, 256>>>(gi1A, gi1B, gi1C, gh1, hL1, out_h1,
                                 post_W, post_b, out_output);
}